// round 13
// baseline (speedup 1.0000x reference)
#include <cuda_runtime.h>
#include <cuda_bf16.h>
#include <cstdint>
#include <math.h>

#define NT 3
#define Bz 8
#define T1c 128
#define T2c 256
#define Cc 256
#define M1 (Bz*T1c)   /* 1024 */
#define M2 (Bz*T2c)   /* 2048 */

#define K3_Q   768
#define K3_KV  832
#define K3_AUX 64

// ---------------- device scratch ----------------
__device__ __align__(16) __nv_bfloat16 d_x13 [M1 * K3_Q];
__device__ __align__(16) __nv_bfloat16 d_x2c3[M2 * K3_KV];
__device__ __align__(16) __nv_bfloat16 d_ax13[M1 * K3_AUX];
__device__ __align__(16) __nv_bfloat16 d_wq3 [NT * Cc * K3_Q];
__device__ __align__(16) __nv_bfloat16 d_wk3 [NT * Cc * K3_KV];
__device__ __align__(16) __nv_bfloat16 d_wv3 [NT * Cc * K3_KV];
__device__ __align__(16) __nv_bfloat16 d_wva3[NT * Cc * K3_AUX];
__device__ __align__(16) __nv_bfloat16 d_wp3 [NT * Cc * K3_Q];
__device__ __align__(16) __nv_bfloat16 d_y3  [NT * M1 * K3_Q];
__device__ __align__(16) __nv_bfloat16 d_qhi[NT*M1*Cc], d_qlo[NT*M1*Cc];
__device__ __align__(16) __nv_bfloat16 d_khi[NT*M2*Cc], d_klo[NT*M2*Cc];
__device__ __align__(16) __nv_bfloat16 d_vhi[NT*M2*Cc], d_vlo[NT*M2*Cc];
__device__ uint32_t d_maskp[NT*Bz*T1c*8];
__device__ float g_vaux[NT * M1 * Cc];
__device__ float g_p [NT * M1 * Cc];
__device__ float g_p2[NT * M1 * Cc];

// ---------------- helpers ----------------
__device__ __forceinline__ uint32_t smem_u32(const void* p) {
    uint32_t a;
    asm("{ .reg .u64 t; cvta.to.shared.u64 t, %1; cvt.u32.u64 %0, t; }" : "=r"(a) : "l"(p));
    return a;
}
#define CP16(sm, gp) asm volatile("cp.async.cg.shared.global [%0], [%1], 16;" :: "r"(sm), "l"(gp))
#define CPC()  asm volatile("cp.async.commit_group;" ::: "memory")
#define CPW2() asm volatile("cp.async.wait_group 2;" ::: "memory")

__device__ __forceinline__ void mma16816(float* c, const uint32_t* a, const uint32_t* b) {
    asm volatile(
        "mma.sync.aligned.m16n8k16.row.col.f32.bf16.bf16.f32 "
        "{%0,%1,%2,%3}, {%4,%5,%6,%7}, {%8,%9}, {%0,%1,%2,%3};"
        : "+f"(c[0]), "+f"(c[1]), "+f"(c[2]), "+f"(c[3])
        : "r"(a[0]), "r"(a[1]), "r"(a[2]), "r"(a[3]), "r"(b[0]), "r"(b[1]));
}
__device__ __forceinline__ uint32_t pack_bf2(float x, float y) {
    __nv_bfloat162 t = __floats2bfloat162_rn(x, y);
    return *(uint32_t*)&t;
}
__device__ __forceinline__ uint32_t pack_bf2_res(float x, float y, uint32_t hi) {
    __nv_bfloat162 h = *(__nv_bfloat162*)&hi;
    return pack_bf2(x - __bfloat162float(h.x), y - __bfloat162float(h.y));
}

// ---------------- fused prep: inputs split + W split + maskpack -------------
#define N_X1 (M1*256)
#define N_X2 (M2*256)
#define N_A2 (M2*16)
#define N_A1 (M1*16)
#define PREP_TOT (N_X1 + N_X2 + N_A2 + N_A1)
#define PREP_BLKS (PREP_TOT/256)
#define PW_BLKS 804
#define MK_BLKS 384
#define PREP_GRID (PREP_BLKS + PW_BLKS + MK_BLKS)

__device__ void prep_inputs_dev(int blk, const float* __restrict__ x1, const float* __restrict__ x2,
                                const float* __restrict__ aux_x1, const float* __restrict__ aux_x2)
{
    int t = blk * 256 + threadIdx.x;
    float v; __nv_bfloat16* base; int o0, o1, o2;
    if (t < N_X1) {
        int m = t >> 8, k = t & 255;
        v = x1[t];
        base = d_x13 + (size_t)m * K3_Q;
        o0 = k; o1 = 256 + k; o2 = 512 + k;
    } else if (t < N_X1 + N_X2) {
        int e = t - N_X1, m = e >> 8, k = e & 255;
        v = x2[e];
        base = d_x2c3 + (size_t)m * K3_KV;
        o0 = k; o1 = 272 + k; o2 = 544 + k;
    } else if (t < N_X1 + N_X2 + N_A2) {
        int e = t - N_X1 - N_X2, m = e >> 4, k = e & 15;
        v = aux_x2[e];
        base = d_x2c3 + (size_t)m * K3_KV;
        o0 = 256 + k; o1 = 272 + 256 + k; o2 = 544 + 256 + k;
    } else {
        int e = t - N_X1 - N_X2 - N_A2, m = e >> 4, k = e & 15;
        v = aux_x1[e];
        base = d_ax13 + (size_t)m * K3_AUX;
        o0 = k; o1 = 16 + k; o2 = 32 + k;
    }
    __nv_bfloat16 hi = __float2bfloat16(v);
    __nv_bfloat16 lo = __float2bfloat16(v - __bfloat162float(hi));
    base[o0] = hi; base[o1] = lo; base[o2] = hi;
}

__device__ void prep_w_dev(int id, const float* __restrict__ Wq, const float* __restrict__ Wk,
                           const float* __restrict__ Wv, const float* __restrict__ Wp)
{
    __shared__ float sT[16][65];
    const float* src; __nv_bfloat16* dst; int Ksrc, K3pad, ktiles, rmode, srcRows, local;
    if (id < 192)      { local = id;       src = Wq; dst = d_wq3;  Ksrc = 256; K3pad = K3_Q;   ktiles = 16; rmode = 0; srcRows = 256; }
    else if (id < 396) { local = id - 192; src = Wk; dst = d_wk3;  Ksrc = 272; K3pad = K3_KV;  ktiles = 17; rmode = 1; srcRows = 288; }
    else if (id < 600) { local = id - 396; src = Wv; dst = d_wv3;  Ksrc = 272; K3pad = K3_KV;  ktiles = 17; rmode = 1; srcRows = 288; }
    else if (id < 612) { local = id - 600; src = Wv; dst = d_wva3; Ksrc = 16;  K3pad = K3_AUX; ktiles = 1;  rmode = 2; srcRows = 288; }
    else               { local = id - 612; src = Wp; dst = d_wp3;  Ksrc = 256; K3pad = K3_Q;   ktiles = 16; rmode = 0; srcRows = 256; }
    const int per = ktiles * 4;
    const int i = local / per, r = local % per;
    const int kb = (r >> 2) * 16, nb = (r & 3) * 64;
    const float* wb = src + (size_t)i * srcRows * 256;
    const int t = threadIdx.x;
#pragma unroll
    for (int rr = 0; rr < 4; ++rr) {
        int kk = rr * 4 + (t >> 6), nn = t & 63;
        int k = kb + kk;
        int row = (rmode == 0) ? k : ((rmode == 1) ? (k < 256 ? k : k + 16) : (256 + k));
        sT[kk][nn] = wb[(size_t)row * 256 + nb + nn];
    }
    __syncthreads();
#pragma unroll
    for (int rr = 0; rr < 4; ++rr) {
        int n2 = rr * 16 + (t >> 4), k2 = t & 15;
        float v = sT[k2][n2];
        __nv_bfloat16 hi = __float2bfloat16(v);
        __nv_bfloat16 lo = __float2bfloat16(v - __bfloat162float(hi));
        size_t base = (size_t)i * 256 * K3pad + (size_t)(nb + n2) * K3pad;
        int k = kb + k2;
        dst[base + k]            = hi;
        dst[base + Ksrc + k]     = hi;
        dst[base + 2 * Ksrc + k] = lo;
    }
}

__device__ void maskpack_dev(int blk, const int* __restrict__ masks)
{
    int row = blk * 8 + (threadIdx.x >> 5);
    int lane = threadIdx.x & 31;
    const int* mrow = masks + (size_t)row * 256;
#pragma unroll
    for (int j = 0; j < 8; ++j) {
        uint32_t w = __ballot_sync(0xffffffffu, mrow[j*32 + lane] != 0);
        if (lane == 0) d_maskp[row*8 + j] = w;
    }
}

__global__ __launch_bounds__(256)
void prep_all_kernel(const float* __restrict__ x1, const float* __restrict__ x2,
                     const float* __restrict__ aux_x1, const float* __restrict__ aux_x2,
                     const float* __restrict__ Wq, const float* __restrict__ Wk,
                     const float* __restrict__ Wv, const float* __restrict__ Wp,
                     const int* __restrict__ masks)
{
    const int id = blockIdx.x;
    if (id < PREP_BLKS)                 prep_inputs_dev(id, x1, x2, aux_x1, aux_x2);
    else if (id < PREP_BLKS + PW_BLKS)  prep_w_dev(id - PREP_BLKS, Wq, Wk, Wv, Wp);
    else                                maskpack_dev(id - PREP_BLKS - PW_BLKS, masks);
}

// ---------------- GEMM engine: (MI*32)x128 tile, K-chunk 32, 4-stage --------
#define GPAD 40
#define NSTG 4
template<int MI>
__device__ __forceinline__ void gemm_stage_load(
    char* stage, const __nv_bfloat16* __restrict__ A, int lda,
    const __nv_bfloat16* __restrict__ B, int ldb, int mb, int nb, int kof, int tid)
{
    __nv_bfloat16 (*sA)[GPAD] = (__nv_bfloat16(*)[GPAD])stage;
    __nv_bfloat16 (*sB)[GPAD] = (__nv_bfloat16(*)[GPAD])(stage + MI*32*GPAD*2);
#pragma unroll
    for (int j = 0; j < MI/2; ++j) {
        int idx = tid + j * 256;
        int row = idx >> 2, c8 = (idx & 3) * 8;
        CP16(smem_u32(&sA[row][c8]), A + (size_t)(mb + row) * lda + kof + c8);
    }
#pragma unroll
    for (int j = 0; j < 2; ++j) {
        int idx = tid + j * 256;
        int row = idx >> 2, c8 = (idx & 3) * 8;
        CP16(smem_u32(&sB[row][c8]), B + (size_t)(nb + row) * ldb + kof + c8);
    }
}

template<int MI>
__device__ __forceinline__ void mma_tile_run(
    const __nv_bfloat16* __restrict__ A, int lda,
    const __nv_bfloat16* __restrict__ B, int ldb,
    int NC, int kBase, float* __restrict__ outF,
    __nv_bfloat16* __restrict__ oHi, __nv_bfloat16* __restrict__ oLo, float scale,
    const float* __restrict__ bias, int mb, int nb)
{
    extern __shared__ __align__(16) char gsm[];
    const int STAGE = (MI*32 + 128) * GPAD * 2;
    float* sBias = (float*)(gsm + NSTG*STAGE);

    const int tid = threadIdx.x;
    const int wid = tid >> 5, lane = tid & 31;
    const int warpM = wid & 1, warpN = wid >> 1;
    const int fr = lane >> 2, qc = lane & 3;

    if (tid < 128) sBias[tid] = bias ? bias[nb + tid] : 0.f;

    float acc[MI][4][4];
#pragma unroll
    for (int mi = 0; mi < MI; ++mi)
#pragma unroll
        for (int ni = 0; ni < 4; ++ni)
#pragma unroll
            for (int q = 0; q < 4; ++q) acc[mi][ni][q] = 0.f;

    // prologue: prefetch chunks 0..2
#pragma unroll
    for (int p = 0; p < 3; ++p) {
        if (p < NC) gemm_stage_load<MI>(gsm + p*STAGE, A, lda, B, ldb, mb, nb, kBase + p*32, tid);
        CPC();
    }

    int st = 0, pf = 3;
    for (int ch = 0; ch < NC; ++ch) {
        CPW2();
        __syncthreads();
        if (ch + 3 < NC)
            gemm_stage_load<MI>(gsm + pf*STAGE, A, lda, B, ldb, mb, nb, kBase + (ch+3)*32, tid);
        CPC();

        __nv_bfloat16 (*sA)[GPAD] = (__nv_bfloat16(*)[GPAD])(gsm + st*STAGE);
        __nv_bfloat16 (*sB)[GPAD] = (__nv_bfloat16(*)[GPAD])(gsm + st*STAGE + MI*32*GPAD*2);
#pragma unroll
        for (int kk = 0; kk < 2; ++kk) {
            const int kc = kk * 16 + qc * 2;
            uint32_t a[MI][4], bb[4][2];
#pragma unroll
            for (int mi = 0; mi < MI; ++mi) {
                const int mr = warpM * (MI*16) + mi * 16 + fr;
                a[mi][0] = *(const uint32_t*)&sA[mr    ][kc];
                a[mi][1] = *(const uint32_t*)&sA[mr + 8][kc];
                a[mi][2] = *(const uint32_t*)&sA[mr    ][kc + 8];
                a[mi][3] = *(const uint32_t*)&sA[mr + 8][kc + 8];
            }
#pragma unroll
            for (int ni = 0; ni < 4; ++ni) {
                const int nr = warpN * 32 + ni * 8 + fr;
                bb[ni][0] = *(const uint32_t*)&sB[nr][kc];
                bb[ni][1] = *(const uint32_t*)&sB[nr][kc + 8];
            }
#pragma unroll
            for (int mi = 0; mi < MI; ++mi)
#pragma unroll
                for (int ni = 0; ni < 4; ++ni)
                    mma16816(acc[mi][ni], a[mi], bb[ni]);
        }
        st = (st == NSTG-1) ? 0 : st + 1;
        pf = (pf == NSTG-1) ? 0 : pf + 1;
    }

#pragma unroll
    for (int mi = 0; mi < MI; ++mi) {
        const int mr0 = mb + warpM * (MI*16) + mi * 16 + fr;
#pragma unroll
        for (int ni = 0; ni < 4; ++ni) {
            const int nloc = warpN * 32 + ni * 8 + qc * 2;
            const int ng = nb + nloc;
            float o00 = acc[mi][ni][0] + sBias[nloc];
            float o01 = acc[mi][ni][1] + sBias[nloc + 1];
            float o10 = acc[mi][ni][2] + sBias[nloc];
            float o11 = acc[mi][ni][3] + sBias[nloc + 1];
            if (outF) {
                *(float2*)(outF + (size_t)mr0 * Cc + ng)       = make_float2(o00, o01);
                *(float2*)(outF + (size_t)(mr0 + 8) * Cc + ng) = make_float2(o10, o11);
            } else {
                o00 *= scale; o01 *= scale; o10 *= scale; o11 *= scale;
                uint32_t h0 = pack_bf2(o00, o01), h1 = pack_bf2(o10, o11);
                uint32_t l0 = pack_bf2_res(o00, o01, h0), l1 = pack_bf2_res(o10, o11, h1);
                *(uint32_t*)(oHi + (size_t)mr0 * Cc + ng)       = h0;
                *(uint32_t*)(oHi + (size_t)(mr0 + 8) * Cc + ng) = h1;
                *(uint32_t*)(oLo + (size_t)mr0 * Cc + ng)       = l0;
                *(uint32_t*)(oLo + (size_t)(mr0 + 8) * Cc + ng) = l1;
            }
        }
    }
}

#define QKV_SMEM  (NSTG*((128+128)*GPAD*2) + 512)   /* 82432 */
#define PROJ_SMEM (NSTG*((64+128)*GPAD*2) + 512)    /* 61952 */
#define QSCALE 0.17677669529663687f

// qkv fused: [0,48) q | [48,144) k | [144,240) v | [240,288) vaux
__global__ __launch_bounds__(256)
void mma_qkv_kernel(const float* __restrict__ bq, const float* __restrict__ bk,
                    const float* __restrict__ bv)
{
    const int id = blockIdx.x;
    if (id < 48) {
        int i = id / 16, r = id % 16, mt = r >> 1, nt = r & 1;
        mma_tile_run<4>(d_x13, K3_Q, d_wq3 + (size_t)i*Cc*K3_Q, K3_Q, 24, 0,
                        nullptr, d_qhi + (size_t)i*M1*Cc, d_qlo + (size_t)i*M1*Cc, QSCALE,
                        bq + i*Cc, mt*128, nt*128);
    } else if (id < 144) {
        int l = id - 48, i = l / 32, r = l % 32, mt = r >> 1, nt = r & 1;
        mma_tile_run<4>(d_x2c3, K3_KV, d_wk3 + (size_t)i*Cc*K3_KV, K3_KV, 26, 0,
                        nullptr, d_khi + (size_t)i*M2*Cc, d_klo + (size_t)i*M2*Cc, 1.f,
                        bk + i*Cc, mt*128, nt*128);
    } else if (id < 240) {
        int l = id - 144, i = l / 32, r = l % 32, mt = r >> 1, nt = r & 1;
        mma_tile_run<4>(d_x2c3, K3_KV, d_wv3 + (size_t)i*Cc*K3_KV, K3_KV, 26, 0,
                        nullptr, d_vhi + (size_t)i*M2*Cc, d_vlo + (size_t)i*M2*Cc, 1.f,
                        bv + i*Cc, mt*128, nt*128);
    } else {
        int l = id - 240, i = l / 16, r = l % 16, mt = r >> 1, nt = r & 1;
        mma_tile_run<4>(d_ax13, K3_AUX, d_wva3 + (size_t)i*Cc*K3_AUX, K3_AUX, 2, 0,
                        g_vaux + (size_t)i*M1*Cc, nullptr, nullptr, 1.f,
                        nullptr, mt*128, nt*128);
    }
}

// proj: 64x128 tiles, split-K 2-way, grid 192
__global__ __launch_bounds__(256)
void mma_proj_kernel()
{
    const int id = blockIdx.x;
    const int s = id / 96;          // split-K half
    const int l = id % 96;
    int i = l / 32, r = l % 32, mt = r >> 1, nt = r & 1;
    float* outp = (s == 0 ? g_p : g_p2) + (size_t)i*M1*Cc;
    mma_tile_run<2>(d_y3 + (size_t)i*M1*K3_Q, K3_Q, d_wp3 + (size_t)i*Cc*K3_Q, K3_Q,
                    12, s*384, outp, nullptr, nullptr, 1.f,
                    nullptr, mt*64, nt*128);
}

// ---------------- flash attention, V transposed in smem ---------------------
#define APAD 40
#define VTP 264
#define OFF_QH 0
#define OFF_QL 10240
#define OFF_KH 20480
#define OFF_KL 40960
#define OFF_VTH 61440
#define OFF_VTL 78336
#define OFF_MK 95232
#define ATTN_SMEM 99328

__global__ __launch_bounds__(256)
void attn_flash_kernel()
{
    extern __shared__ __align__(16) char dsm[];
    __nv_bfloat16 (*sQh)[APAD] = (__nv_bfloat16(*)[APAD])(dsm + OFF_QH);
    __nv_bfloat16 (*sQl)[APAD] = (__nv_bfloat16(*)[APAD])(dsm + OFF_QL);
    __nv_bfloat16 (*sKh)[APAD] = (__nv_bfloat16(*)[APAD])(dsm + OFF_KH);
    __nv_bfloat16 (*sKl)[APAD] = (__nv_bfloat16(*)[APAD])(dsm + OFF_KL);
    __nv_bfloat16 (*sVTh)[VTP] = (__nv_bfloat16(*)[VTP])(dsm + OFF_VTH);
    __nv_bfloat16 (*sVTl)[VTP] = (__nv_bfloat16(*)[VTP])(dsm + OFF_VTL);
    uint32_t (*sMask)[8] = (uint32_t(*)[8])(dsm + OFF_MK);

    const int h = blockIdx.x, b = blockIdx.y, i = blockIdx.z;
    const int tid = threadIdx.x;
    const int warp = tid >> 5, lane = tid & 31;
    const int fr = lane >> 2, qc = lane & 3;
    const int r0 = warp * 16;

    const size_t qoff = ((size_t)(i*Bz + b) * T1c) * Cc + h*32;
    const size_t koff = ((size_t)(i*Bz + b) * T2c) * Cc + h*32;

#pragma unroll
    for (int j = 0; j < 2; ++j) {
        int idx = tid + j * 256;
        int row = idx >> 2, c8 = (idx & 3) * 8;
        *(float4*)&sQh[row][c8] = *(const float4*)(d_qhi + qoff + (size_t)row*Cc + c8);
        *(float4*)&sQl[row][c8] = *(const float4*)(d_qlo + qoff + (size_t)row*Cc + c8);
    }
#pragma unroll
    for (int j = 0; j < 4; ++j) {
        int idx = tid + j * 256;
        int row = idx >> 2, c8 = (idx & 3) * 8;
        *(float4*)&sKh[row][c8] = *(const float4*)(d_khi + koff + (size_t)row*Cc + c8);
        *(float4*)&sKl[row][c8] = *(const float4*)(d_klo + koff + (size_t)row*Cc + c8);
        float4 vh4 = *(const float4*)(d_vhi + koff + (size_t)row*Cc + c8);
        float4 vl4 = *(const float4*)(d_vlo + koff + (size_t)row*Cc + c8);
        const __nv_bfloat16* vh = (const __nv_bfloat16*)&vh4;
        const __nv_bfloat16* vl = (const __nv_bfloat16*)&vl4;
#pragma unroll
        for (int jj = 0; jj < 8; ++jj) {
            sVTh[c8 + jj][row] = vh[jj];
            sVTl[c8 + jj][row] = vl[jj];
        }
    }
#pragma unroll
    for (int j = 0; j < 4; ++j) {
        int w = tid + j * 256;
        ((uint32_t*)(dsm + OFF_MK))[w] = d_maskp[(size_t)(i*Bz + b)*1024 + w];
    }
    __syncthreads();

    float m0 = -1e30f, m1 = -1e30f, l0 = 0.f, l1 = 0.f;
    float Y[4][4];
#pragma unroll
    for (int n = 0; n < 4; ++n)
#pragma unroll
        for (int q = 0; q < 4; ++q) Y[n][q] = 0.f;

    for (int ch = 0; ch < 4; ++ch) {
        float sc[8][4];
#pragma unroll
        for (int n = 0; n < 8; ++n)
#pragma unroll
            for (int q = 0; q < 4; ++q) sc[n][q] = 0.f;

#pragma unroll
        for (int term = 0; term < 3; ++term) {
            __nv_bfloat16 (*Aq)[APAD] = (term == 1) ? sQl : sQh;
            __nv_bfloat16 (*Bk)[APAD] = (term == 2) ? sKl : sKh;
#pragma unroll
            for (int kk = 0; kk < 2; ++kk) {
                const int kc = kk * 16 + qc * 2;
                uint32_t a[4];
                a[0] = *(const uint32_t*)&Aq[r0 + fr    ][kc];
                a[1] = *(const uint32_t*)&Aq[r0 + fr + 8][kc];
                a[2] = *(const uint32_t*)&Aq[r0 + fr    ][kc + 8];
                a[3] = *(const uint32_t*)&Aq[r0 + fr + 8][kc + 8];
#pragma unroll
                for (int nt = 0; nt < 8; ++nt) {
                    const int tr = ch*64 + nt*8 + fr;
                    uint32_t bb[2];
                    bb[0] = *(const uint32_t*)&Bk[tr][kc];
                    bb[1] = *(const uint32_t*)&Bk[tr][kc + 8];
                    mma16816(sc[nt], a, bb);
                }
            }
        }

        uint32_t w0a = sMask[r0 + fr    ][2*ch], w0b = sMask[r0 + fr    ][2*ch + 1];
        uint32_t w1a = sMask[r0 + fr + 8][2*ch], w1b = sMask[r0 + fr + 8][2*ch + 1];
#pragma unroll
        for (int nt = 0; nt < 8; ++nt) {
            uint32_t wr0 = (nt < 4) ? w0a : w0b;
            uint32_t wr1 = (nt < 4) ? w1a : w1b;
            const int bbase = (nt & 3) * 8 + qc * 2;
            if (!((wr0 >> bbase) & 1))       sc[nt][0] = -1e30f;
            if (!((wr0 >> (bbase+1)) & 1))   sc[nt][1] = -1e30f;
            if (!((wr1 >> bbase) & 1))       sc[nt][2] = -1e30f;
            if (!((wr1 >> (bbase+1)) & 1))   sc[nt][3] = -1e30f;
        }

        float rx0 = -1e30f, rx1 = -1e30f;
#pragma unroll
        for (int nt = 0; nt < 8; ++nt) {
            rx0 = fmaxf(rx0, fmaxf(sc[nt][0], sc[nt][1]));
            rx1 = fmaxf(rx1, fmaxf(sc[nt][2], sc[nt][3]));
        }
#pragma unroll
        for (int o = 1; o <= 2; o <<= 1) {
            rx0 = fmaxf(rx0, __shfl_xor_sync(0xffffffffu, rx0, o));
            rx1 = fmaxf(rx1, __shfl_xor_sync(0xffffffffu, rx1, o));
        }
        const float mn0 = fmaxf(m0, rx0), mn1 = fmaxf(m1, rx1);
        const float al0 = __expf(m0 - mn0), al1 = __expf(m1 - mn1);
        const float z0 = (mn0 <= -1e29f) ? 0.f : 1.f;
        const float z1 = (mn1 <= -1e29f) ? 0.f : 1.f;
        float s0 = 0.f, s1 = 0.f;
#pragma unroll
        for (int nt = 0; nt < 8; ++nt) {
            sc[nt][0] = __expf(sc[nt][0] - mn0) * z0;
            sc[nt][1] = __expf(sc[nt][1] - mn0) * z0;
            sc[nt][2] = __expf(sc[nt][2] - mn1) * z1;
            sc[nt][3] = __expf(sc[nt][3] - mn1) * z1;
            s0 += sc[nt][0] + sc[nt][1];
            s1 += sc[nt][2] + sc[nt][3];
        }
#pragma unroll
        for (int o = 1; o <= 2; o <<= 1) {
            s0 += __shfl_xor_sync(0xffffffffu, s0, o);
            s1 += __shfl_xor_sync(0xffffffffu, s1, o);
        }
        l0 = l0 * al0 + s0;
        l1 = l1 * al1 + s1;
        m0 = mn0; m1 = mn1;
#pragma unroll
        for (int n = 0; n < 4; ++n) {
            Y[n][0] *= al0; Y[n][1] *= al0;
            Y[n][2] *= al1; Y[n][3] *= al1;
        }

        uint32_t ah[4][4], alo[4][4];
#pragma unroll
        for (int kt = 0; kt < 4; ++kt) {
            const int f0 = 2*kt, f1 = 2*kt + 1;
            ah[kt][0] = pack_bf2(sc[f0][0], sc[f0][1]);
            ah[kt][1] = pack_bf2(sc[f0][2], sc[f0][3]);
            ah[kt][2] = pack_bf2(sc[f1][0], sc[f1][1]);
            ah[kt][3] = pack_bf2(sc[f1][2], sc[f1][3]);
            alo[kt][0] = pack_bf2_res(sc[f0][0], sc[f0][1], ah[kt][0]);
            alo[kt][1] = pack_bf2_res(sc[f0][2], sc[f0][3], ah[kt][1]);
            alo[kt][2] = pack_bf2_res(sc[f1][0], sc[f1][1], ah[kt][2]);
            alo[kt][3] = pack_bf2_res(sc[f1][2], sc[f1][3], ah[kt][3]);
        }

#pragma unroll
        for (int term = 0; term < 3; ++term) {
            uint32_t (*Ap)[4] = (term == 1) ? alo : ah;
            __nv_bfloat16 (*Bv)[VTP] = (term == 2) ? sVTl : sVTh;
#pragma unroll
            for (int kt = 0; kt < 4; ++kt) {
#pragma unroll
                for (int nt = 0; nt < 4; ++nt) {
                    const int k0 = ch*64 + kt*16 + qc*2;
                    const int n  = nt*8 + fr;
                    uint32_t bb[2];
                    bb[0] = *(const uint32_t*)&Bv[n][k0];
                    bb[1] = *(const uint32_t*)&Bv[n][k0 + 8];
                    mma16816(Y[nt], Ap[kt], bb);
                }
            }
        }
    }

    float inv0 = (l0 > 0.f) ? 1.f / l0 : 0.f;
    float inv1 = (l1 > 0.f) ? 1.f / l1 : 0.f;
    if (l0 == 0.f) {
#pragma unroll
        for (int nt = 0; nt < 4; ++nt)
            for (int jj = 0; jj < 2; ++jj) {
                int col = nt*8 + qc*2 + jj;
                float s = 0.f;
                for (int t = 0; t < 256; ++t)
                    s += __bfloat162float(sVTh[col][t]) + __bfloat162float(sVTl[col][t]);
                Y[nt][jj] = s * (1.f/256.f);
            }
        inv0 = 1.f;
    }
    if (l1 == 0.f) {
#pragma unroll
        for (int nt = 0; nt < 4; ++nt)
            for (int jj = 0; jj < 2; ++jj) {
                int col = nt*8 + qc*2 + jj;
                float s = 0.f;
                for (int t = 0; t < 256; ++t)
                    s += __bfloat162float(sVTh[col][t]) + __bfloat162float(sVTl[col][t]);
                Y[nt][2 + jj] = s * (1.f/256.f);
            }
        inv1 = 1.f;
    }

    const int row0 = r0 + fr, row1 = r0 + fr + 8;
    const float* vx0 = g_vaux + ((size_t)(i*Bz + b)*T1c + row0) * Cc + h*32;
    const float* vx1 = g_vaux + ((size_t)(i*Bz + b)*T1c + row1) * Cc + h*32;
    __nv_bfloat16* y0 = d_y3 + (size_t)i*M1*K3_Q + (size_t)(b*T1c + row0)*K3_Q + h*32;
    __nv_bfloat16* y1 = d_y3 + (size_t)i*M1*K3_Q + (size_t)(b*T1c + row1)*K3_Q + h*32;
#pragma unroll
    for (int nt = 0; nt < 4; ++nt) {
        const int c0 = nt*8 + qc*2;
        float2 v0 = *(const float2*)(vx0 + c0);
        float2 v1 = *(const float2*)(vx1 + c0);
        float o00 = Y[nt][0]*inv0 + v0.x, o01 = Y[nt][1]*inv0 + v0.y;
        float o10 = Y[nt][2]*inv1 + v1.x, o11 = Y[nt][3]*inv1 + v1.y;
        uint32_t h0 = pack_bf2(o00, o01), l0p = pack_bf2_res(o00, o01, h0);
        uint32_t h1 = pack_bf2(o10, o11), l1p = pack_bf2_res(o10, o11, h1);
        *(uint32_t*)(y0 + c0)       = h0;
        *(uint32_t*)(y0 + 256 + c0) = l0p;
        *(uint32_t*)(y0 + 512 + c0) = h0;
        *(uint32_t*)(y1 + c0)       = h1;
        *(uint32_t*)(y1 + 256 + c0) = l1p;
        *(uint32_t*)(y1 + 512 + c0) = h1;
    }
}

// ---------------- final sum: 6 planes + biases ----------------
__global__ void sum_kernel(const float* __restrict__ bp, float* __restrict__ out)
{
    int e = blockIdx.x * 256 + threadIdx.x;
    int col4 = (e & 63) * 4;
    float4 o = make_float4(0.f, 0.f, 0.f, 0.f);
#pragma unroll
    for (int i = 0; i < NT; ++i) {
        float4 pa = *(const float4*)(g_p  + (size_t)i*M1*Cc + (size_t)e*4);
        float4 pb = *(const float4*)(g_p2 + (size_t)i*M1*Cc + (size_t)e*4);
        float4 bi = *(const float4*)(bp + i*256 + col4);
        o.x += pa.x + pb.x + bi.x;
        o.y += pa.y + pb.y + bi.y;
        o.z += pa.z + pb.z + bi.z;
        o.w += pa.w + pb.w + bi.w;
    }
    *(float4*)(out + (size_t)e*4) = o;
}

// ---------------- launch ----------------
extern "C" void kernel_launch(void* const* d_in, const int* in_sizes, int n_in,
                              void* d_out, int out_size)
{
    const float* x1     = (const float*)d_in[0];
    const float* x2     = (const float*)d_in[1];
    const float* aux_x1 = (const float*)d_in[2];
    const float* aux_x2 = (const float*)d_in[3];
    const int*   masks  = (const int*)  d_in[4];
    const float* Wq     = (const float*)d_in[5];
    const float* bq     = (const float*)d_in[6];
    const float* Wk     = (const float*)d_in[7];
    const float* bk     = (const float*)d_in[8];
    const float* Wv     = (const float*)d_in[9];
    const float* bv     = (const float*)d_in[10];
    const float* Wp     = (const float*)d_in[11];
    const float* bp     = (const float*)d_in[12];
    float* out = (float*)d_out;

    cudaFuncSetAttribute(attn_flash_kernel,
                         cudaFuncAttributeMaxDynamicSharedMemorySize, ATTN_SMEM);
    cudaFuncSetAttribute(mma_qkv_kernel,
                         cudaFuncAttributeMaxDynamicSharedMemorySize, QKV_SMEM);
    cudaFuncSetAttribute(mma_proj_kernel,
                         cudaFuncAttributeMaxDynamicSharedMemorySize, PROJ_SMEM);

    prep_all_kernel<<<PREP_GRID, 256>>>(x1, x2, aux_x1, aux_x2, Wq, Wk, Wv, Wp, masks);
    mma_qkv_kernel<<<288, 256, QKV_SMEM>>>(bq, bk, bv);
    attn_flash_kernel<<<dim3(8, Bz, NT), 256, ATTN_SMEM>>>();
    mma_proj_kernel<<<192, 256, PROJ_SMEM>>>();
    sum_kernel<<<256, 256>>>(bp, out);
}

// round 14
// speedup vs baseline: 1.5261x; 1.5261x over previous
#include <cuda_runtime.h>
#include <cuda_bf16.h>
#include <cstdint>
#include <math.h>

#define NT 3
#define Bz 8
#define T1c 128
#define T2c 256
#define Cc 256
#define M1 (Bz*T1c)   /* 1024 */
#define M2 (Bz*T2c)   /* 2048 */

#define K3_Q   768
#define K3_KV  832
#define K3_AUX 64

// ---------------- device scratch ----------------
__device__ __align__(16) __nv_bfloat16 d_x13 [M1 * K3_Q];
__device__ __align__(16) __nv_bfloat16 d_x2c3[M2 * K3_KV];
__device__ __align__(16) __nv_bfloat16 d_ax13[M1 * K3_AUX];
__device__ __align__(16) __nv_bfloat16 d_wq3 [NT * Cc * K3_Q];
__device__ __align__(16) __nv_bfloat16 d_wk3 [NT * Cc * K3_KV];
__device__ __align__(16) __nv_bfloat16 d_wv3 [NT * Cc * K3_KV];
__device__ __align__(16) __nv_bfloat16 d_wva3[NT * Cc * K3_AUX];
__device__ __align__(16) __nv_bfloat16 d_wp3 [NT * Cc * K3_Q];
__device__ __align__(16) __nv_bfloat16 d_y3  [NT * M1 * K3_Q];
__device__ __align__(16) __nv_bfloat16 d_qhi[NT*M1*Cc], d_qlo[NT*M1*Cc];
__device__ __align__(16) __nv_bfloat16 d_khi[NT*M2*Cc], d_klo[NT*M2*Cc];
__device__ __align__(16) __nv_bfloat16 d_vhi[NT*M2*Cc], d_vlo[NT*M2*Cc];
__device__ uint32_t d_maskp[NT*Bz*T1c*8];
__device__ float g_vaux[NT * M1 * Cc];
__device__ float g_p [NT * M1 * Cc];
__device__ float g_p2[NT * M1 * Cc];

// ---------------- helpers ----------------
__device__ __forceinline__ uint32_t smem_u32(const void* p) {
    uint32_t a;
    asm("{ .reg .u64 t; cvta.to.shared.u64 t, %1; cvt.u32.u64 %0, t; }" : "=r"(a) : "l"(p));
    return a;
}
#define CP16(sm, gp) asm volatile("cp.async.cg.shared.global [%0], [%1], 16;" :: "r"(sm), "l"(gp))
#define CPC()  asm volatile("cp.async.commit_group;" ::: "memory")
#define CPW1() asm volatile("cp.async.wait_group 1;" ::: "memory")

__device__ __forceinline__ void mma16816(float* c, const uint32_t* a, const uint32_t* b) {
    asm volatile(
        "mma.sync.aligned.m16n8k16.row.col.f32.bf16.bf16.f32 "
        "{%0,%1,%2,%3}, {%4,%5,%6,%7}, {%8,%9}, {%0,%1,%2,%3};"
        : "+f"(c[0]), "+f"(c[1]), "+f"(c[2]), "+f"(c[3])
        : "r"(a[0]), "r"(a[1]), "r"(a[2]), "r"(a[3]), "r"(b[0]), "r"(b[1]));
}
__device__ __forceinline__ uint32_t pack_bf2(float x, float y) {
    __nv_bfloat162 t = __floats2bfloat162_rn(x, y);
    return *(uint32_t*)&t;
}
__device__ __forceinline__ uint32_t pack_bf2_res(float x, float y, uint32_t hi) {
    __nv_bfloat162 h = *(__nv_bfloat162*)&hi;
    return pack_bf2(x - __bfloat162float(h.x), y - __bfloat162float(h.y));
}

// ---------------- fused prep: inputs split + W split + maskpack -------------
#define N_X1 (M1*256)
#define N_X2 (M2*256)
#define N_A2 (M2*16)
#define N_A1 (M1*16)
#define PREP_TOT (N_X1 + N_X2 + N_A2 + N_A1)
#define PREP_BLKS (PREP_TOT/256)
#define PW_BLKS 804
#define MK_BLKS 384
#define PREP_GRID (PREP_BLKS + PW_BLKS + MK_BLKS)

__device__ void prep_inputs_dev(int blk, const float* __restrict__ x1, const float* __restrict__ x2,
                                const float* __restrict__ aux_x1, const float* __restrict__ aux_x2)
{
    int t = blk * 256 + threadIdx.x;
    float v; __nv_bfloat16* base; int o0, o1, o2;
    if (t < N_X1) {
        int m = t >> 8, k = t & 255;
        v = x1[t];
        base = d_x13 + (size_t)m * K3_Q;
        o0 = k; o1 = 256 + k; o2 = 512 + k;
    } else if (t < N_X1 + N_X2) {
        int e = t - N_X1, m = e >> 8, k = e & 255;
        v = x2[e];
        base = d_x2c3 + (size_t)m * K3_KV;
        o0 = k; o1 = 272 + k; o2 = 544 + k;
    } else if (t < N_X1 + N_X2 + N_A2) {
        int e = t - N_X1 - N_X2, m = e >> 4, k = e & 15;
        v = aux_x2[e];
        base = d_x2c3 + (size_t)m * K3_KV;
        o0 = 256 + k; o1 = 272 + 256 + k; o2 = 544 + 256 + k;
    } else {
        int e = t - N_X1 - N_X2 - N_A2, m = e >> 4, k = e & 15;
        v = aux_x1[e];
        base = d_ax13 + (size_t)m * K3_AUX;
        o0 = k; o1 = 16 + k; o2 = 32 + k;
    }
    __nv_bfloat16 hi = __float2bfloat16(v);
    __nv_bfloat16 lo = __float2bfloat16(v - __bfloat162float(hi));
    base[o0] = hi; base[o1] = lo; base[o2] = hi;
}

__device__ void prep_w_dev(int id, const float* __restrict__ Wq, const float* __restrict__ Wk,
                           const float* __restrict__ Wv, const float* __restrict__ Wp)
{
    __shared__ float sT[16][65];
    const float* src; __nv_bfloat16* dst; int Ksrc, K3pad, ktiles, rmode, srcRows, local;
    if (id < 192)      { local = id;       src = Wq; dst = d_wq3;  Ksrc = 256; K3pad = K3_Q;   ktiles = 16; rmode = 0; srcRows = 256; }
    else if (id < 396) { local = id - 192; src = Wk; dst = d_wk3;  Ksrc = 272; K3pad = K3_KV;  ktiles = 17; rmode = 1; srcRows = 288; }
    else if (id < 600) { local = id - 396; src = Wv; dst = d_wv3;  Ksrc = 272; K3pad = K3_KV;  ktiles = 17; rmode = 1; srcRows = 288; }
    else if (id < 612) { local = id - 600; src = Wv; dst = d_wva3; Ksrc = 16;  K3pad = K3_AUX; ktiles = 1;  rmode = 2; srcRows = 288; }
    else               { local = id - 612; src = Wp; dst = d_wp3;  Ksrc = 256; K3pad = K3_Q;   ktiles = 16; rmode = 0; srcRows = 256; }
    const int per = ktiles * 4;
    const int i = local / per, r = local % per;
    const int kb = (r >> 2) * 16, nb = (r & 3) * 64;
    const float* wb = src + (size_t)i * srcRows * 256;
    const int t = threadIdx.x;
#pragma unroll
    for (int rr = 0; rr < 4; ++rr) {
        int kk = rr * 4 + (t >> 6), nn = t & 63;
        int k = kb + kk;
        int row = (rmode == 0) ? k : ((rmode == 1) ? (k < 256 ? k : k + 16) : (256 + k));
        sT[kk][nn] = wb[(size_t)row * 256 + nb + nn];
    }
    __syncthreads();
#pragma unroll
    for (int rr = 0; rr < 4; ++rr) {
        int n2 = rr * 16 + (t >> 4), k2 = t & 15;
        float v = sT[k2][n2];
        __nv_bfloat16 hi = __float2bfloat16(v);
        __nv_bfloat16 lo = __float2bfloat16(v - __bfloat162float(hi));
        size_t base = (size_t)i * 256 * K3pad + (size_t)(nb + n2) * K3pad;
        int k = kb + k2;
        dst[base + k]            = hi;
        dst[base + Ksrc + k]     = hi;
        dst[base + 2 * Ksrc + k] = lo;
    }
}

__device__ void maskpack_dev(int blk, const int* __restrict__ masks)
{
    int row = blk * 8 + (threadIdx.x >> 5);
    int lane = threadIdx.x & 31;
    const int* mrow = masks + (size_t)row * 256;
#pragma unroll
    for (int j = 0; j < 8; ++j) {
        uint32_t w = __ballot_sync(0xffffffffu, mrow[j*32 + lane] != 0);
        if (lane == 0) d_maskp[row*8 + j] = w;
    }
}

__global__ __launch_bounds__(256)
void prep_all_kernel(const float* __restrict__ x1, const float* __restrict__ x2,
                     const float* __restrict__ aux_x1, const float* __restrict__ aux_x2,
                     const float* __restrict__ Wq, const float* __restrict__ Wk,
                     const float* __restrict__ Wv, const float* __restrict__ Wp,
                     const int* __restrict__ masks)
{
    const int id = blockIdx.x;
    if (id < PREP_BLKS)                 prep_inputs_dev(id, x1, x2, aux_x1, aux_x2);
    else if (id < PREP_BLKS + PW_BLKS)  prep_w_dev(id - PREP_BLKS, Wq, Wk, Wv, Wp);
    else                                maskpack_dev(id - PREP_BLKS - PW_BLKS, masks);
}

// ---------------- GEMM engine: (MI*32)x128 tile, K-chunk 32, 3-stage --------
#define GPAD 40
template<int MI>
__device__ __forceinline__ void gemm_stage_load(
    char* stage, const __nv_bfloat16* __restrict__ A, int lda,
    const __nv_bfloat16* __restrict__ B, int ldb, int mb, int nb, int kof, int tid)
{
    __nv_bfloat16 (*sA)[GPAD] = (__nv_bfloat16(*)[GPAD])stage;
    __nv_bfloat16 (*sB)[GPAD] = (__nv_bfloat16(*)[GPAD])(stage + MI*32*GPAD*2);
#pragma unroll
    for (int j = 0; j < MI/2; ++j) {
        int idx = tid + j * 256;
        int row = idx >> 2, c8 = (idx & 3) * 8;
        CP16(smem_u32(&sA[row][c8]), A + (size_t)(mb + row) * lda + kof + c8);
    }
#pragma unroll
    for (int j = 0; j < 2; ++j) {
        int idx = tid + j * 256;
        int row = idx >> 2, c8 = (idx & 3) * 8;
        CP16(smem_u32(&sB[row][c8]), B + (size_t)(nb + row) * ldb + kof + c8);
    }
}

template<int MI>
__device__ __forceinline__ void mma_tile_run(
    const __nv_bfloat16* __restrict__ A, int lda,
    const __nv_bfloat16* __restrict__ B, int ldb,
    int NC, int kBase, float* __restrict__ outF,
    __nv_bfloat16* __restrict__ oHi, __nv_bfloat16* __restrict__ oLo, float scale,
    const float* __restrict__ bias, int mb, int nb)
{
    extern __shared__ __align__(16) char gsm[];
    const int STAGE = (MI*32 + 128) * GPAD * 2;
    float* sBias = (float*)(gsm + 3*STAGE);

    const int tid = threadIdx.x;
    const int wid = tid >> 5, lane = tid & 31;
    const int warpM = wid & 1, warpN = wid >> 1;
    const int fr = lane >> 2, qc = lane & 3;

    if (tid < 128) sBias[tid] = bias ? bias[nb + tid] : 0.f;

    float acc[MI][4][4];
#pragma unroll
    for (int mi = 0; mi < MI; ++mi)
#pragma unroll
        for (int ni = 0; ni < 4; ++ni)
#pragma unroll
            for (int q = 0; q < 4; ++q) acc[mi][ni][q] = 0.f;

    gemm_stage_load<MI>(gsm, A, lda, B, ldb, mb, nb, kBase, tid);
    CPC();
    if (NC > 1) gemm_stage_load<MI>(gsm + STAGE, A, lda, B, ldb, mb, nb, kBase + 32, tid);
    CPC();

    int st = 0, pf = 2;
    for (int ch = 0; ch < NC; ++ch) {
        CPW1();
        __syncthreads();
        if (ch + 2 < NC)
            gemm_stage_load<MI>(gsm + pf*STAGE, A, lda, B, ldb, mb, nb, kBase + (ch+2)*32, tid);
        CPC();

        __nv_bfloat16 (*sA)[GPAD] = (__nv_bfloat16(*)[GPAD])(gsm + st*STAGE);
        __nv_bfloat16 (*sB)[GPAD] = (__nv_bfloat16(*)[GPAD])(gsm + st*STAGE + MI*32*GPAD*2);
#pragma unroll
        for (int kk = 0; kk < 2; ++kk) {
            const int kc = kk * 16 + qc * 2;
            uint32_t a[MI][4], bb[4][2];
#pragma unroll
            for (int mi = 0; mi < MI; ++mi) {
                const int mr = warpM * (MI*16) + mi * 16 + fr;
                a[mi][0] = *(const uint32_t*)&sA[mr    ][kc];
                a[mi][1] = *(const uint32_t*)&sA[mr + 8][kc];
                a[mi][2] = *(const uint32_t*)&sA[mr    ][kc + 8];
                a[mi][3] = *(const uint32_t*)&sA[mr + 8][kc + 8];
            }
#pragma unroll
            for (int ni = 0; ni < 4; ++ni) {
                const int nr = warpN * 32 + ni * 8 + fr;
                bb[ni][0] = *(const uint32_t*)&sB[nr][kc];
                bb[ni][1] = *(const uint32_t*)&sB[nr][kc + 8];
            }
#pragma unroll
            for (int mi = 0; mi < MI; ++mi)
#pragma unroll
                for (int ni = 0; ni < 4; ++ni)
                    mma16816(acc[mi][ni], a[mi], bb[ni]);
        }
        st = (st == 2) ? 0 : st + 1;
        pf = (pf == 2) ? 0 : pf + 1;
    }

#pragma unroll
    for (int mi = 0; mi < MI; ++mi) {
        const int mr0 = mb + warpM * (MI*16) + mi * 16 + fr;
#pragma unroll
        for (int ni = 0; ni < 4; ++ni) {
            const int nloc = warpN * 32 + ni * 8 + qc * 2;
            const int ng = nb + nloc;
            float o00 = acc[mi][ni][0] + sBias[nloc];
            float o01 = acc[mi][ni][1] + sBias[nloc + 1];
            float o10 = acc[mi][ni][2] + sBias[nloc];
            float o11 = acc[mi][ni][3] + sBias[nloc + 1];
            if (outF) {
                *(float2*)(outF + (size_t)mr0 * Cc + ng)       = make_float2(o00, o01);
                *(float2*)(outF + (size_t)(mr0 + 8) * Cc + ng) = make_float2(o10, o11);
            } else {
                o00 *= scale; o01 *= scale; o10 *= scale; o11 *= scale;
                uint32_t h0 = pack_bf2(o00, o01), h1 = pack_bf2(o10, o11);
                uint32_t l0 = pack_bf2_res(o00, o01, h0), l1 = pack_bf2_res(o10, o11, h1);
                *(uint32_t*)(oHi + (size_t)mr0 * Cc + ng)       = h0;
                *(uint32_t*)(oHi + (size_t)(mr0 + 8) * Cc + ng) = h1;
                *(uint32_t*)(oLo + (size_t)mr0 * Cc + ng)       = l0;
                *(uint32_t*)(oLo + (size_t)(mr0 + 8) * Cc + ng) = l1;
            }
        }
    }
}

#define QKV_SMEM  (3*((128+128)*GPAD*2) + 512)   /* 61952 */
#define PROJ_SMEM (3*((64+128)*GPAD*2) + 512)    /* 46592 */
#define QSCALE 0.17677669529663687f

// qkv fused: [0,48) q | [48,144) k | [144,240) v | [240,288) vaux
__global__ __launch_bounds__(256)
void mma_qkv_kernel(const float* __restrict__ bq, const float* __restrict__ bk,
                    const float* __restrict__ bv)
{
    const int id = blockIdx.x;
    if (id < 48) {
        int i = id / 16, r = id % 16, mt = r >> 1, nt = r & 1;
        mma_tile_run<4>(d_x13, K3_Q, d_wq3 + (size_t)i*Cc*K3_Q, K3_Q, 24, 0,
                        nullptr, d_qhi + (size_t)i*M1*Cc, d_qlo + (size_t)i*M1*Cc, QSCALE,
                        bq + i*Cc, mt*128, nt*128);
    } else if (id < 144) {
        int l = id - 48, i = l / 32, r = l % 32, mt = r >> 1, nt = r & 1;
        mma_tile_run<4>(d_x2c3, K3_KV, d_wk3 + (size_t)i*Cc*K3_KV, K3_KV, 26, 0,
                        nullptr, d_khi + (size_t)i*M2*Cc, d_klo + (size_t)i*M2*Cc, 1.f,
                        bk + i*Cc, mt*128, nt*128);
    } else if (id < 240) {
        int l = id - 144, i = l / 32, r = l % 32, mt = r >> 1, nt = r & 1;
        mma_tile_run<4>(d_x2c3, K3_KV, d_wv3 + (size_t)i*Cc*K3_KV, K3_KV, 26, 0,
                        nullptr, d_vhi + (size_t)i*M2*Cc, d_vlo + (size_t)i*M2*Cc, 1.f,
                        bv + i*Cc, mt*128, nt*128);
    } else {
        int l = id - 240, i = l / 16, r = l % 16, mt = r >> 1, nt = r & 1;
        mma_tile_run<4>(d_ax13, K3_AUX, d_wva3 + (size_t)i*Cc*K3_AUX, K3_AUX, 2, 0,
                        g_vaux + (size_t)i*M1*Cc, nullptr, nullptr, 1.f,
                        nullptr, mt*128, nt*128);
    }
}

// proj: 64x128 tiles, split-K 2-way on the 3-stage engine, grid 192
__global__ __launch_bounds__(256)
void mma_proj_kernel()
{
    const int id = blockIdx.x;
    const int s = id / 96;
    const int l = id % 96;
    int i = l / 32, r = l % 32, mt = r >> 1, nt = r & 1;
    float* outp = (s == 0 ? g_p : g_p2) + (size_t)i*M1*Cc;
    mma_tile_run<2>(d_y3 + (size_t)i*M1*K3_Q, K3_Q, d_wp3 + (size_t)i*Cc*K3_Q, K3_Q,
                    12, s*384, outp, nullptr, nullptr, 1.f,
                    nullptr, mt*64, nt*128);
}

// ---------------- flash attention, V transposed in smem ---------------------
#define APAD 40
#define VTP 264
#define OFF_QH 0
#define OFF_QL 10240
#define OFF_KH 20480
#define OFF_KL 40960
#define OFF_VTH 61440
#define OFF_VTL 78336
#define OFF_MK 95232
#define ATTN_SMEM 99328

__global__ __launch_bounds__(256)
void attn_flash_kernel()
{
    extern __shared__ __align__(16) char dsm[];
    __nv_bfloat16 (*sQh)[APAD] = (__nv_bfloat16(*)[APAD])(dsm + OFF_QH);
    __nv_bfloat16 (*sQl)[APAD] = (__nv_bfloat16(*)[APAD])(dsm + OFF_QL);
    __nv_bfloat16 (*sKh)[APAD] = (__nv_bfloat16(*)[APAD])(dsm + OFF_KH);
    __nv_bfloat16 (*sKl)[APAD] = (__nv_bfloat16(*)[APAD])(dsm + OFF_KL);
    __nv_bfloat16 (*sVTh)[VTP] = (__nv_bfloat16(*)[VTP])(dsm + OFF_VTH);
    __nv_bfloat16 (*sVTl)[VTP] = (__nv_bfloat16(*)[VTP])(dsm + OFF_VTL);
    uint32_t (*sMask)[8] = (uint32_t(*)[8])(dsm + OFF_MK);

    const int h = blockIdx.x, b = blockIdx.y, i = blockIdx.z;
    const int tid = threadIdx.x;
    const int warp = tid >> 5, lane = tid & 31;
    const int fr = lane >> 2, qc = lane & 3;
    const int r0 = warp * 16;

    const size_t qoff = ((size_t)(i*Bz + b) * T1c) * Cc + h*32;
    const size_t koff = ((size_t)(i*Bz + b) * T2c) * Cc + h*32;

#pragma unroll
    for (int j = 0; j < 2; ++j) {
        int idx = tid + j * 256;
        int row = idx >> 2, c8 = (idx & 3) * 8;
        *(float4*)&sQh[row][c8] = *(const float4*)(d_qhi + qoff + (size_t)row*Cc + c8);
        *(float4*)&sQl[row][c8] = *(const float4*)(d_qlo + qoff + (size_t)row*Cc + c8);
    }
#pragma unroll
    for (int j = 0; j < 4; ++j) {
        int idx = tid + j * 256;
        int row = idx >> 2, c8 = (idx & 3) * 8;
        *(float4*)&sKh[row][c8] = *(const float4*)(d_khi + koff + (size_t)row*Cc + c8);
        *(float4*)&sKl[row][c8] = *(const float4*)(d_klo + koff + (size_t)row*Cc + c8);
        float4 vh4 = *(const float4*)(d_vhi + koff + (size_t)row*Cc + c8);
        float4 vl4 = *(const float4*)(d_vlo + koff + (size_t)row*Cc + c8);
        const __nv_bfloat16* vh = (const __nv_bfloat16*)&vh4;
        const __nv_bfloat16* vl = (const __nv_bfloat16*)&vl4;
#pragma unroll
        for (int jj = 0; jj < 8; ++jj) {
            sVTh[c8 + jj][row] = vh[jj];
            sVTl[c8 + jj][row] = vl[jj];
        }
    }
#pragma unroll
    for (int j = 0; j < 4; ++j) {
        int w = tid + j * 256;
        ((uint32_t*)(dsm + OFF_MK))[w] = d_maskp[(size_t)(i*Bz + b)*1024 + w];
    }
    __syncthreads();

    float m0 = -1e30f, m1 = -1e30f, l0 = 0.f, l1 = 0.f;
    float Y[4][4];
#pragma unroll
    for (int n = 0; n < 4; ++n)
#pragma unroll
        for (int q = 0; q < 4; ++q) Y[n][q] = 0.f;

    for (int ch = 0; ch < 4; ++ch) {
        float sc[8][4];
#pragma unroll
        for (int n = 0; n < 8; ++n)
#pragma unroll
            for (int q = 0; q < 4; ++q) sc[n][q] = 0.f;

#pragma unroll
        for (int term = 0; term < 3; ++term) {
            __nv_bfloat16 (*Aq)[APAD] = (term == 1) ? sQl : sQh;
            __nv_bfloat16 (*Bk)[APAD] = (term == 2) ? sKl : sKh;
#pragma unroll
            for (int kk = 0; kk < 2; ++kk) {
                const int kc = kk * 16 + qc * 2;
                uint32_t a[4];
                a[0] = *(const uint32_t*)&Aq[r0 + fr    ][kc];
                a[1] = *(const uint32_t*)&Aq[r0 + fr + 8][kc];
                a[2] = *(const uint32_t*)&Aq[r0 + fr    ][kc + 8];
                a[3] = *(const uint32_t*)&Aq[r0 + fr + 8][kc + 8];
#pragma unroll
                for (int nt = 0; nt < 8; ++nt) {
                    const int tr = ch*64 + nt*8 + fr;
                    uint32_t bb[2];
                    bb[0] = *(const uint32_t*)&Bk[tr][kc];
                    bb[1] = *(const uint32_t*)&Bk[tr][kc + 8];
                    mma16816(sc[nt], a, bb);
                }
            }
        }

        uint32_t w0a = sMask[r0 + fr    ][2*ch], w0b = sMask[r0 + fr    ][2*ch + 1];
        uint32_t w1a = sMask[r0 + fr + 8][2*ch], w1b = sMask[r0 + fr + 8][2*ch + 1];
#pragma unroll
        for (int nt = 0; nt < 8; ++nt) {
            uint32_t wr0 = (nt < 4) ? w0a : w0b;
            uint32_t wr1 = (nt < 4) ? w1a : w1b;
            const int bbase = (nt & 3) * 8 + qc * 2;
            if (!((wr0 >> bbase) & 1))       sc[nt][0] = -1e30f;
            if (!((wr0 >> (bbase+1)) & 1))   sc[nt][1] = -1e30f;
            if (!((wr1 >> bbase) & 1))       sc[nt][2] = -1e30f;
            if (!((wr1 >> (bbase+1)) & 1))   sc[nt][3] = -1e30f;
        }

        float rx0 = -1e30f, rx1 = -1e30f;
#pragma unroll
        for (int nt = 0; nt < 8; ++nt) {
            rx0 = fmaxf(rx0, fmaxf(sc[nt][0], sc[nt][1]));
            rx1 = fmaxf(rx1, fmaxf(sc[nt][2], sc[nt][3]));
        }
#pragma unroll
        for (int o = 1; o <= 2; o <<= 1) {
            rx0 = fmaxf(rx0, __shfl_xor_sync(0xffffffffu, rx0, o));
            rx1 = fmaxf(rx1, __shfl_xor_sync(0xffffffffu, rx1, o));
        }
        const float mn0 = fmaxf(m0, rx0), mn1 = fmaxf(m1, rx1);
        const float al0 = __expf(m0 - mn0), al1 = __expf(m1 - mn1);
        const float z0 = (mn0 <= -1e29f) ? 0.f : 1.f;
        const float z1 = (mn1 <= -1e29f) ? 0.f : 1.f;
        float s0 = 0.f, s1 = 0.f;
#pragma unroll
        for (int nt = 0; nt < 8; ++nt) {
            sc[nt][0] = __expf(sc[nt][0] - mn0) * z0;
            sc[nt][1] = __expf(sc[nt][1] - mn0) * z0;
            sc[nt][2] = __expf(sc[nt][2] - mn1) * z1;
            sc[nt][3] = __expf(sc[nt][3] - mn1) * z1;
            s0 += sc[nt][0] + sc[nt][1];
            s1 += sc[nt][2] + sc[nt][3];
        }
#pragma unroll
        for (int o = 1; o <= 2; o <<= 1) {
            s0 += __shfl_xor_sync(0xffffffffu, s0, o);
            s1 += __shfl_xor_sync(0xffffffffu, s1, o);
        }
        l0 = l0 * al0 + s0;
        l1 = l1 * al1 + s1;
        m0 = mn0; m1 = mn1;
#pragma unroll
        for (int n = 0; n < 4; ++n) {
            Y[n][0] *= al0; Y[n][1] *= al0;
            Y[n][2] *= al1; Y[n][3] *= al1;
        }

        uint32_t ah[4][4], alo[4][4];
#pragma unroll
        for (int kt = 0; kt < 4; ++kt) {
            const int f0 = 2*kt, f1 = 2*kt + 1;
            ah[kt][0] = pack_bf2(sc[f0][0], sc[f0][1]);
            ah[kt][1] = pack_bf2(sc[f0][2], sc[f0][3]);
            ah[kt][2] = pack_bf2(sc[f1][0], sc[f1][1]);
            ah[kt][3] = pack_bf2(sc[f1][2], sc[f1][3]);
            alo[kt][0] = pack_bf2_res(sc[f0][0], sc[f0][1], ah[kt][0]);
            alo[kt][1] = pack_bf2_res(sc[f0][2], sc[f0][3], ah[kt][1]);
            alo[kt][2] = pack_bf2_res(sc[f1][0], sc[f1][1], ah[kt][2]);
            alo[kt][3] = pack_bf2_res(sc[f1][2], sc[f1][3], ah[kt][3]);
        }

#pragma unroll
        for (int term = 0; term < 3; ++term) {
            uint32_t (*Ap)[4] = (term == 1) ? alo : ah;
            __nv_bfloat16 (*Bv)[VTP] = (term == 2) ? sVTl : sVTh;
#pragma unroll
            for (int kt = 0; kt < 4; ++kt) {
#pragma unroll
                for (int nt = 0; nt < 4; ++nt) {
                    const int k0 = ch*64 + kt*16 + qc*2;
                    const int n  = nt*8 + fr;
                    uint32_t bb[2];
                    bb[0] = *(const uint32_t*)&Bv[n][k0];
                    bb[1] = *(const uint32_t*)&Bv[n][k0 + 8];
                    mma16816(Y[nt], Ap[kt], bb);
                }
            }
        }
    }

    float inv0 = (l0 > 0.f) ? 1.f / l0 : 0.f;
    float inv1 = (l1 > 0.f) ? 1.f / l1 : 0.f;
    if (l0 == 0.f) {
#pragma unroll
        for (int nt = 0; nt < 4; ++nt)
            for (int jj = 0; jj < 2; ++jj) {
                int col = nt*8 + qc*2 + jj;
                float s = 0.f;
                for (int t = 0; t < 256; ++t)
                    s += __bfloat162float(sVTh[col][t]) + __bfloat162float(sVTl[col][t]);
                Y[nt][jj] = s * (1.f/256.f);
            }
        inv0 = 1.f;
    }
    if (l1 == 0.f) {
#pragma unroll
        for (int nt = 0; nt < 4; ++nt)
            for (int jj = 0; jj < 2; ++jj) {
                int col = nt*8 + qc*2 + jj;
                float s = 0.f;
                for (int t = 0; t < 256; ++t)
                    s += __bfloat162float(sVTh[col][t]) + __bfloat162float(sVTl[col][t]);
                Y[nt][2 + jj] = s * (1.f/256.f);
            }
        inv1 = 1.f;
    }

    const int row0 = r0 + fr, row1 = r0 + fr + 8;
    const float* vx0 = g_vaux + ((size_t)(i*Bz + b)*T1c + row0) * Cc + h*32;
    const float* vx1 = g_vaux + ((size_t)(i*Bz + b)*T1c + row1) * Cc + h*32;
    __nv_bfloat16* y0 = d_y3 + (size_t)i*M1*K3_Q + (size_t)(b*T1c + row0)*K3_Q + h*32;
    __nv_bfloat16* y1 = d_y3 + (size_t)i*M1*K3_Q + (size_t)(b*T1c + row1)*K3_Q + h*32;
#pragma unroll
    for (int nt = 0; nt < 4; ++nt) {
        const int c0 = nt*8 + qc*2;
        float2 v0 = *(const float2*)(vx0 + c0);
        float2 v1 = *(const float2*)(vx1 + c0);
        float o00 = Y[nt][0]*inv0 + v0.x, o01 = Y[nt][1]*inv0 + v0.y;
        float o10 = Y[nt][2]*inv1 + v1.x, o11 = Y[nt][3]*inv1 + v1.y;
        uint32_t h0 = pack_bf2(o00, o01), l0p = pack_bf2_res(o00, o01, h0);
        uint32_t h1 = pack_bf2(o10, o11), l1p = pack_bf2_res(o10, o11, h1);
        *(uint32_t*)(y0 + c0)       = h0;
        *(uint32_t*)(y0 + 256 + c0) = l0p;
        *(uint32_t*)(y0 + 512 + c0) = h0;
        *(uint32_t*)(y1 + c0)       = h1;
        *(uint32_t*)(y1 + 256 + c0) = l1p;
        *(uint32_t*)(y1 + 512 + c0) = h1;
    }
}

// ---------------- final sum: 6 planes + biases ----------------
__global__ void sum_kernel(const float* __restrict__ bp, float* __restrict__ out)
{
    int e = blockIdx.x * 256 + threadIdx.x;
    int col4 = (e & 63) * 4;
    float4 o = make_float4(0.f, 0.f, 0.f, 0.f);
#pragma unroll
    for (int i = 0; i < NT; ++i) {
        float4 pa = *(const float4*)(g_p  + (size_t)i*M1*Cc + (size_t)e*4);
        float4 pb = *(const float4*)(g_p2 + (size_t)i*M1*Cc + (size_t)e*4);
        float4 bi = *(const float4*)(bp + i*256 + col4);
        o.x += pa.x + pb.x + bi.x;
        o.y += pa.y + pb.y + bi.y;
        o.z += pa.z + pb.z + bi.z;
        o.w += pa.w + pb.w + bi.w;
    }
    *(float4*)(out + (size_t)e*4) = o;
}

// ---------------- launch ----------------
extern "C" void kernel_launch(void* const* d_in, const int* in_sizes, int n_in,
                              void* d_out, int out_size)
{
    const float* x1     = (const float*)d_in[0];
    const float* x2     = (const float*)d_in[1];
    const float* aux_x1 = (const float*)d_in[2];
    const float* aux_x2 = (const float*)d_in[3];
    const int*   masks  = (const int*)  d_in[4];
    const float* Wq     = (const float*)d_in[5];
    const float* bq     = (const float*)d_in[6];
    const float* Wk     = (const float*)d_in[7];
    const float* bk     = (const float*)d_in[8];
    const float* Wv     = (const float*)d_in[9];
    const float* bv     = (const float*)d_in[10];
    const float* Wp     = (const float*)d_in[11];
    const float* bp     = (const float*)d_in[12];
    float* out = (float*)d_out;

    cudaFuncSetAttribute(attn_flash_kernel,
                         cudaFuncAttributeMaxDynamicSharedMemorySize, ATTN_SMEM);
    cudaFuncSetAttribute(mma_qkv_kernel,
                         cudaFuncAttributeMaxDynamicSharedMemorySize, QKV_SMEM);
    cudaFuncSetAttribute(mma_proj_kernel,
                         cudaFuncAttributeMaxDynamicSharedMemorySize, PROJ_SMEM);

    prep_all_kernel<<<PREP_GRID, 256>>>(x1, x2, aux_x1, aux_x2, Wq, Wk, Wv, Wp, masks);
    mma_qkv_kernel<<<288, 256, QKV_SMEM>>>(bq, bk, bv);
    attn_flash_kernel<<<dim3(8, Bz, NT), 256, ATTN_SMEM>>>();
    mma_proj_kernel<<<192, 256, PROJ_SMEM>>>();
    sum_kernel<<<256, 256>>>(bp, out);
}

// round 15
// speedup vs baseline: 1.5891x; 1.0413x over previous
#include <cuda_runtime.h>
#include <cuda_bf16.h>
#include <cstdint>
#include <math.h>

#define NT 3
#define Bz 8
#define T1c 128
#define T2c 256
#define Cc 256
#define M1 (Bz*T1c)   /* 1024 */
#define M2 (Bz*T2c)   /* 2048 */

#define K3_Q   768
#define K3_KV  832
#define K3_AUX 64
#define K2_Y   512    /* y stored as [hi|lo] */

// ---------------- device scratch ----------------
__device__ __align__(16) __nv_bfloat16 d_x13 [M1 * K3_Q];
__device__ __align__(16) __nv_bfloat16 d_x2c3[M2 * K3_KV];
__device__ __align__(16) __nv_bfloat16 d_ax13[M1 * K3_AUX];
__device__ __align__(16) __nv_bfloat16 d_wq3 [NT * Cc * K3_Q];
__device__ __align__(16) __nv_bfloat16 d_wk3 [NT * Cc * K3_KV];
__device__ __align__(16) __nv_bfloat16 d_wv3 [NT * Cc * K3_KV];
__device__ __align__(16) __nv_bfloat16 d_wva3[NT * Cc * K3_AUX];
__device__ __align__(16) __nv_bfloat16 d_wp3 [NT * Cc * K3_Q];
__device__ __align__(16) __nv_bfloat16 d_y3  [NT * M1 * K2_Y];
__device__ __align__(16) __nv_bfloat16 d_qhi[NT*M1*Cc], d_qlo[NT*M1*Cc];
__device__ __align__(16) __nv_bfloat16 d_khi[NT*M2*Cc], d_klo[NT*M2*Cc];
__device__ __align__(16) __nv_bfloat16 d_vhi[NT*M2*Cc], d_vlo[NT*M2*Cc];
__device__ uint32_t d_maskp[NT*Bz*T1c*8];
__device__ float g_vaux[NT * M1 * Cc];
__device__ float g_pp[4][NT * M1 * Cc];

// ---------------- helpers ----------------
__device__ __forceinline__ uint32_t smem_u32(const void* p) {
    uint32_t a;
    asm("{ .reg .u64 t; cvta.to.shared.u64 t, %1; cvt.u32.u64 %0, t; }" : "=r"(a) : "l"(p));
    return a;
}
#define CP16(sm, gp) asm volatile("cp.async.cg.shared.global [%0], [%1], 16;" :: "r"(sm), "l"(gp))
#define CPC()  asm volatile("cp.async.commit_group;" ::: "memory")
#define CPW1() asm volatile("cp.async.wait_group 1;" ::: "memory")

__device__ __forceinline__ void mma16816(float* c, const uint32_t* a, const uint32_t* b) {
    asm volatile(
        "mma.sync.aligned.m16n8k16.row.col.f32.bf16.bf16.f32 "
        "{%0,%1,%2,%3}, {%4,%5,%6,%7}, {%8,%9}, {%0,%1,%2,%3};"
        : "+f"(c[0]), "+f"(c[1]), "+f"(c[2]), "+f"(c[3])
        : "r"(a[0]), "r"(a[1]), "r"(a[2]), "r"(a[3]), "r"(b[0]), "r"(b[1]));
}
__device__ __forceinline__ uint32_t pack_bf2(float x, float y) {
    __nv_bfloat162 t = __floats2bfloat162_rn(x, y);
    return *(uint32_t*)&t;
}
__device__ __forceinline__ uint32_t pack_bf2_res(float x, float y, uint32_t hi) {
    __nv_bfloat162 h = *(__nv_bfloat162*)&hi;
    return pack_bf2(x - __bfloat162float(h.x), y - __bfloat162float(h.y));
}

// ---------------- fused prep: inputs split + W split + maskpack -------------
#define N_X1 (M1*256)
#define N_X2 (M2*256)
#define N_A2 (M2*16)
#define N_A1 (M1*16)
#define PREP_TOT (N_X1 + N_X2 + N_A2 + N_A1)
#define PREP_BLKS (PREP_TOT/256)
#define PW_BLKS 804
#define MK_BLKS 384
#define PREP_GRID (PREP_BLKS + PW_BLKS + MK_BLKS)

__device__ void prep_inputs_dev(int blk, const float* __restrict__ x1, const float* __restrict__ x2,
                                const float* __restrict__ aux_x1, const float* __restrict__ aux_x2)
{
    int t = blk * 256 + threadIdx.x;
    float v; __nv_bfloat16* base; int o0, o1, o2;
    if (t < N_X1) {
        int m = t >> 8, k = t & 255;
        v = x1[t];
        base = d_x13 + (size_t)m * K3_Q;
        o0 = k; o1 = 256 + k; o2 = 512 + k;
    } else if (t < N_X1 + N_X2) {
        int e = t - N_X1, m = e >> 8, k = e & 255;
        v = x2[e];
        base = d_x2c3 + (size_t)m * K3_KV;
        o0 = k; o1 = 272 + k; o2 = 544 + k;
    } else if (t < N_X1 + N_X2 + N_A2) {
        int e = t - N_X1 - N_X2, m = e >> 4, k = e & 15;
        v = aux_x2[e];
        base = d_x2c3 + (size_t)m * K3_KV;
        o0 = 256 + k; o1 = 272 + 256 + k; o2 = 544 + 256 + k;
    } else {
        int e = t - N_X1 - N_X2 - N_A2, m = e >> 4, k = e & 15;
        v = aux_x1[e];
        base = d_ax13 + (size_t)m * K3_AUX;
        o0 = k; o1 = 16 + k; o2 = 32 + k;
    }
    __nv_bfloat16 hi = __float2bfloat16(v);
    __nv_bfloat16 lo = __float2bfloat16(v - __bfloat162float(hi));
    base[o0] = hi; base[o1] = lo; base[o2] = hi;
}

__device__ void prep_w_dev(int id, const float* __restrict__ Wq, const float* __restrict__ Wk,
                           const float* __restrict__ Wv, const float* __restrict__ Wp)
{
    __shared__ float sT[16][65];
    const float* src; __nv_bfloat16* dst; int Ksrc, K3pad, ktiles, rmode, srcRows, local;
    if (id < 192)      { local = id;       src = Wq; dst = d_wq3;  Ksrc = 256; K3pad = K3_Q;   ktiles = 16; rmode = 0; srcRows = 256; }
    else if (id < 396) { local = id - 192; src = Wk; dst = d_wk3;  Ksrc = 272; K3pad = K3_KV;  ktiles = 17; rmode = 1; srcRows = 288; }
    else if (id < 600) { local = id - 396; src = Wv; dst = d_wv3;  Ksrc = 272; K3pad = K3_KV;  ktiles = 17; rmode = 1; srcRows = 288; }
    else if (id < 612) { local = id - 600; src = Wv; dst = d_wva3; Ksrc = 16;  K3pad = K3_AUX; ktiles = 1;  rmode = 2; srcRows = 288; }
    else               { local = id - 612; src = Wp; dst = d_wp3;  Ksrc = 256; K3pad = K3_Q;   ktiles = 16; rmode = 0; srcRows = 256; }
    const int per = ktiles * 4;
    const int i = local / per, r = local % per;
    const int kb = (r >> 2) * 16, nb = (r & 3) * 64;
    const float* wb = src + (size_t)i * srcRows * 256;
    const int t = threadIdx.x;
#pragma unroll
    for (int rr = 0; rr < 4; ++rr) {
        int kk = rr * 4 + (t >> 6), nn = t & 63;
        int k = kb + kk;
        int row = (rmode == 0) ? k : ((rmode == 1) ? (k < 256 ? k : k + 16) : (256 + k));
        sT[kk][nn] = wb[(size_t)row * 256 + nb + nn];
    }
    __syncthreads();
#pragma unroll
    for (int rr = 0; rr < 4; ++rr) {
        int n2 = rr * 16 + (t >> 4), k2 = t & 15;
        float v = sT[k2][n2];
        __nv_bfloat16 hi = __float2bfloat16(v);
        __nv_bfloat16 lo = __float2bfloat16(v - __bfloat162float(hi));
        size_t base = (size_t)i * 256 * K3pad + (size_t)(nb + n2) * K3pad;
        int k = kb + k2;
        dst[base + k]            = hi;
        dst[base + Ksrc + k]     = hi;
        dst[base + 2 * Ksrc + k] = lo;
    }
}

__device__ void maskpack_dev(int blk, const int* __restrict__ masks)
{
    int row = blk * 8 + (threadIdx.x >> 5);
    int lane = threadIdx.x & 31;
    const int* mrow = masks + (size_t)row * 256;
#pragma unroll
    for (int j = 0; j < 8; ++j) {
        uint32_t w = __ballot_sync(0xffffffffu, mrow[j*32 + lane] != 0);
        if (lane == 0) d_maskp[row*8 + j] = w;
    }
}

__global__ __launch_bounds__(256)
void prep_all_kernel(const float* __restrict__ x1, const float* __restrict__ x2,
                     const float* __restrict__ aux_x1, const float* __restrict__ aux_x2,
                     const float* __restrict__ Wq, const float* __restrict__ Wk,
                     const float* __restrict__ Wv, const float* __restrict__ Wp,
                     const int* __restrict__ masks)
{
    const int id = blockIdx.x;
    if (id < PREP_BLKS)                 prep_inputs_dev(id, x1, x2, aux_x1, aux_x2);
    else if (id < PREP_BLKS + PW_BLKS)  prep_w_dev(id - PREP_BLKS, Wq, Wk, Wv, Wp);
    else                                maskpack_dev(id - PREP_BLKS - PW_BLKS, masks);
}

// ---------------- GEMM engine: (MI*32)x128 tile, K-chunk 32, 3-stage --------
// A chunk offsets can be remapped (proj re-reads hi region for chunks >= 16).
#define GPAD 40
template<int MI>
__device__ __forceinline__ void gemm_stage_load(
    char* stage, const __nv_bfloat16* __restrict__ A, int lda,
    const __nv_bfloat16* __restrict__ B, int ldb, int mb, int nb,
    int kofA, int kofB, int tid)
{
    __nv_bfloat16 (*sA)[GPAD] = (__nv_bfloat16(*)[GPAD])stage;
    __nv_bfloat16 (*sB)[GPAD] = (__nv_bfloat16(*)[GPAD])(stage + MI*32*GPAD*2);
#pragma unroll
    for (int j = 0; j < MI/2; ++j) {
        int idx = tid + j * 256;
        int row = idx >> 2, c8 = (idx & 3) * 8;
        CP16(smem_u32(&sA[row][c8]), A + (size_t)(mb + row) * lda + kofA + c8);
    }
#pragma unroll
    for (int j = 0; j < 2; ++j) {
        int idx = tid + j * 256;
        int row = idx >> 2, c8 = (idx & 3) * 8;
        CP16(smem_u32(&sB[row][c8]), B + (size_t)(nb + row) * ldb + kofB + c8);
    }
}

template<int MI, int REMAP_A>
__device__ __forceinline__ void mma_tile_run(
    const __nv_bfloat16* __restrict__ A, int lda,
    const __nv_bfloat16* __restrict__ B, int ldb,
    int NC, int chBase, float* __restrict__ outF,
    __nv_bfloat16* __restrict__ oHi, __nv_bfloat16* __restrict__ oLo, float scale,
    const float* __restrict__ bias, int mb, int nb)
{
    extern __shared__ __align__(16) char gsm[];
    const int STAGE = (MI*32 + 128) * GPAD * 2;
    float* sBias = (float*)(gsm + 3*STAGE);

    const int tid = threadIdx.x;
    const int wid = tid >> 5, lane = tid & 31;
    const int warpM = wid & 1, warpN = wid >> 1;
    const int fr = lane >> 2, qc = lane & 3;

    if (tid < 128) sBias[tid] = bias ? bias[nb + tid] : 0.f;

    float acc[MI][4][4];
#pragma unroll
    for (int mi = 0; mi < MI; ++mi)
#pragma unroll
        for (int ni = 0; ni < 4; ++ni)
#pragma unroll
            for (int q = 0; q < 4; ++q) acc[mi][ni][q] = 0.f;

    auto kA = [&](int g) { return (REMAP_A && g >= 16) ? (g - 16) * 32 : g * 32; };

    gemm_stage_load<MI>(gsm, A, lda, B, ldb, mb, nb, kA(chBase), chBase*32, tid);
    CPC();
    if (NC > 1) gemm_stage_load<MI>(gsm + STAGE, A, lda, B, ldb, mb, nb,
                                    kA(chBase+1), (chBase+1)*32, tid);
    CPC();

    int st = 0, pf = 2;
    for (int ch = 0; ch < NC; ++ch) {
        CPW1();
        __syncthreads();
        if (ch + 2 < NC) {
            int g = chBase + ch + 2;
            gemm_stage_load<MI>(gsm + pf*STAGE, A, lda, B, ldb, mb, nb, kA(g), g*32, tid);
        }
        CPC();

        __nv_bfloat16 (*sA)[GPAD] = (__nv_bfloat16(*)[GPAD])(gsm + st*STAGE);
        __nv_bfloat16 (*sB)[GPAD] = (__nv_bfloat16(*)[GPAD])(gsm + st*STAGE + MI*32*GPAD*2);
#pragma unroll
        for (int kk = 0; kk < 2; ++kk) {
            const int kc = kk * 16 + qc * 2;
            uint32_t a[MI][4], bb[4][2];
#pragma unroll
            for (int mi = 0; mi < MI; ++mi) {
                const int mr = warpM * (MI*16) + mi * 16 + fr;
                a[mi][0] = *(const uint32_t*)&sA[mr    ][kc];
                a[mi][1] = *(const uint32_t*)&sA[mr + 8][kc];
                a[mi][2] = *(const uint32_t*)&sA[mr    ][kc + 8];
                a[mi][3] = *(const uint32_t*)&sA[mr + 8][kc + 8];
            }
#pragma unroll
            for (int ni = 0; ni < 4; ++ni) {
                const int nr = warpN * 32 + ni * 8 + fr;
                bb[ni][0] = *(const uint32_t*)&sB[nr][kc];
                bb[ni][1] = *(const uint32_t*)&sB[nr][kc + 8];
            }
#pragma unroll
            for (int mi = 0; mi < MI; ++mi)
#pragma unroll
                for (int ni = 0; ni < 4; ++ni)
                    mma16816(acc[mi][ni], a[mi], bb[ni]);
        }
        st = (st == 2) ? 0 : st + 1;
        pf = (pf == 2) ? 0 : pf + 1;
    }

#pragma unroll
    for (int mi = 0; mi < MI; ++mi) {
        const int mr0 = mb + warpM * (MI*16) + mi * 16 + fr;
#pragma unroll
        for (int ni = 0; ni < 4; ++ni) {
            const int nloc = warpN * 32 + ni * 8 + qc * 2;
            const int ng = nb + nloc;
            float o00 = acc[mi][ni][0] + sBias[nloc];
            float o01 = acc[mi][ni][1] + sBias[nloc + 1];
            float o10 = acc[mi][ni][2] + sBias[nloc];
            float o11 = acc[mi][ni][3] + sBias[nloc + 1];
            if (outF) {
                *(float2*)(outF + (size_t)mr0 * Cc + ng)       = make_float2(o00, o01);
                *(float2*)(outF + (size_t)(mr0 + 8) * Cc + ng) = make_float2(o10, o11);
            } else {
                o00 *= scale; o01 *= scale; o10 *= scale; o11 *= scale;
                uint32_t h0 = pack_bf2(o00, o01), h1 = pack_bf2(o10, o11);
                uint32_t l0 = pack_bf2_res(o00, o01, h0), l1 = pack_bf2_res(o10, o11, h1);
                *(uint32_t*)(oHi + (size_t)mr0 * Cc + ng)       = h0;
                *(uint32_t*)(oHi + (size_t)(mr0 + 8) * Cc + ng) = h1;
                *(uint32_t*)(oLo + (size_t)mr0 * Cc + ng)       = l0;
                *(uint32_t*)(oLo + (size_t)(mr0 + 8) * Cc + ng) = l1;
            }
        }
    }
}

#define QKV_SMEM  (3*((128+128)*GPAD*2) + 512)   /* 61952 */
#define PROJ_SMEM (3*((64+128)*GPAD*2) + 512)    /* 46592 */
#define QSCALE 0.17677669529663687f

// qkv fused: [0,48) q | [48,144) k | [144,240) v | [240,288) vaux
__global__ __launch_bounds__(256)
void mma_qkv_kernel(const float* __restrict__ bq, const float* __restrict__ bk,
                    const float* __restrict__ bv)
{
    const int id = blockIdx.x;
    if (id < 48) {
        int i = id / 16, r = id % 16, mt = r >> 1, nt = r & 1;
        mma_tile_run<4,0>(d_x13, K3_Q, d_wq3 + (size_t)i*Cc*K3_Q, K3_Q, 24, 0,
                          nullptr, d_qhi + (size_t)i*M1*Cc, d_qlo + (size_t)i*M1*Cc, QSCALE,
                          bq + i*Cc, mt*128, nt*128);
    } else if (id < 144) {
        int l = id - 48, i = l / 32, r = l % 32, mt = r >> 1, nt = r & 1;
        mma_tile_run<4,0>(d_x2c3, K3_KV, d_wk3 + (size_t)i*Cc*K3_KV, K3_KV, 26, 0,
                          nullptr, d_khi + (size_t)i*M2*Cc, d_klo + (size_t)i*M2*Cc, 1.f,
                          bk + i*Cc, mt*128, nt*128);
    } else if (id < 240) {
        int l = id - 144, i = l / 32, r = l % 32, mt = r >> 1, nt = r & 1;
        mma_tile_run<4,0>(d_x2c3, K3_KV, d_wv3 + (size_t)i*Cc*K3_KV, K3_KV, 26, 0,
                          nullptr, d_vhi + (size_t)i*M2*Cc, d_vlo + (size_t)i*M2*Cc, 1.f,
                          bv + i*Cc, mt*128, nt*128);
    } else {
        int l = id - 240, i = l / 16, r = l % 16, mt = r >> 1, nt = r & 1;
        mma_tile_run<4,0>(d_ax13, K3_AUX, d_wva3 + (size_t)i*Cc*K3_AUX, K3_AUX, 2, 0,
                          g_vaux + (size_t)i*M1*Cc, nullptr, nullptr, 1.f,
                          nullptr, mt*128, nt*128);
    }
}

// proj: 64x128 tiles, split-K 4-way, A stored [hi|lo] with chunk remap, grid 384
__global__ __launch_bounds__(256)
void mma_proj_kernel()
{
    const int id = blockIdx.x;
    const int s = id / 96;          // split-K quarter: chunks [s*6, s*6+6)
    const int l = id % 96;
    int i = l / 32, r = l % 32, mt = r >> 1, nt = r & 1;
    float* outp = g_pp[s] + (size_t)i*M1*Cc;
    mma_tile_run<2,1>(d_y3 + (size_t)i*M1*K2_Y, K2_Y, d_wp3 + (size_t)i*Cc*K3_Q, K3_Q,
                      6, s*6, outp, nullptr, nullptr, 1.f,
                      nullptr, mt*64, nt*128);
}

// ---------------- flash attention, V transposed in smem ---------------------
#define APAD 40
#define VTP 264
#define OFF_QH 0
#define OFF_QL 10240
#define OFF_KH 20480
#define OFF_KL 40960
#define OFF_VTH 61440
#define OFF_VTL 78336
#define OFF_MK 95232
#define ATTN_SMEM 99328

__global__ __launch_bounds__(256)
void attn_flash_kernel()
{
    extern __shared__ __align__(16) char dsm[];
    __nv_bfloat16 (*sQh)[APAD] = (__nv_bfloat16(*)[APAD])(dsm + OFF_QH);
    __nv_bfloat16 (*sQl)[APAD] = (__nv_bfloat16(*)[APAD])(dsm + OFF_QL);
    __nv_bfloat16 (*sKh)[APAD] = (__nv_bfloat16(*)[APAD])(dsm + OFF_KH);
    __nv_bfloat16 (*sKl)[APAD] = (__nv_bfloat16(*)[APAD])(dsm + OFF_KL);
    __nv_bfloat16 (*sVTh)[VTP] = (__nv_bfloat16(*)[VTP])(dsm + OFF_VTH);
    __nv_bfloat16 (*sVTl)[VTP] = (__nv_bfloat16(*)[VTP])(dsm + OFF_VTL);
    uint32_t (*sMask)[8] = (uint32_t(*)[8])(dsm + OFF_MK);

    const int h = blockIdx.x, b = blockIdx.y, i = blockIdx.z;
    const int tid = threadIdx.x;
    const int warp = tid >> 5, lane = tid & 31;
    const int fr = lane >> 2, qc = lane & 3;
    const int r0 = warp * 16;

    const size_t qoff = ((size_t)(i*Bz + b) * T1c) * Cc + h*32;
    const size_t koff = ((size_t)(i*Bz + b) * T2c) * Cc + h*32;

#pragma unroll
    for (int j = 0; j < 2; ++j) {
        int idx = tid + j * 256;
        int row = idx >> 2, c8 = (idx & 3) * 8;
        *(float4*)&sQh[row][c8] = *(const float4*)(d_qhi + qoff + (size_t)row*Cc + c8);
        *(float4*)&sQl[row][c8] = *(const float4*)(d_qlo + qoff + (size_t)row*Cc + c8);
    }
#pragma unroll
    for (int j = 0; j < 4; ++j) {
        int idx = tid + j * 256;
        int row = idx >> 2, c8 = (idx & 3) * 8;
        *(float4*)&sKh[row][c8] = *(const float4*)(d_khi + koff + (size_t)row*Cc + c8);
        *(float4*)&sKl[row][c8] = *(const float4*)(d_klo + koff + (size_t)row*Cc + c8);
        float4 vh4 = *(const float4*)(d_vhi + koff + (size_t)row*Cc + c8);
        float4 vl4 = *(const float4*)(d_vlo + koff + (size_t)row*Cc + c8);
        const __nv_bfloat16* vh = (const __nv_bfloat16*)&vh4;
        const __nv_bfloat16* vl = (const __nv_bfloat16*)&vl4;
#pragma unroll
        for (int jj = 0; jj < 8; ++jj) {
            sVTh[c8 + jj][row] = vh[jj];
            sVTl[c8 + jj][row] = vl[jj];
        }
    }
#pragma unroll
    for (int j = 0; j < 4; ++j) {
        int w = tid + j * 256;
        ((uint32_t*)(dsm + OFF_MK))[w] = d_maskp[(size_t)(i*Bz + b)*1024 + w];
    }
    __syncthreads();

    float m0 = -1e30f, m1 = -1e30f, l0 = 0.f, l1 = 0.f;
    float Y[4][4];
#pragma unroll
    for (int n = 0; n < 4; ++n)
#pragma unroll
        for (int q = 0; q < 4; ++q) Y[n][q] = 0.f;

    for (int ch = 0; ch < 4; ++ch) {
        float sc[8][4];
#pragma unroll
        for (int n = 0; n < 8; ++n)
#pragma unroll
            for (int q = 0; q < 4; ++q) sc[n][q] = 0.f;

#pragma unroll
        for (int term = 0; term < 3; ++term) {
            __nv_bfloat16 (*Aq)[APAD] = (term == 1) ? sQl : sQh;
            __nv_bfloat16 (*Bk)[APAD] = (term == 2) ? sKl : sKh;
#pragma unroll
            for (int kk = 0; kk < 2; ++kk) {
                const int kc = kk * 16 + qc * 2;
                uint32_t a[4];
                a[0] = *(const uint32_t*)&Aq[r0 + fr    ][kc];
                a[1] = *(const uint32_t*)&Aq[r0 + fr + 8][kc];
                a[2] = *(const uint32_t*)&Aq[r0 + fr    ][kc + 8];
                a[3] = *(const uint32_t*)&Aq[r0 + fr + 8][kc + 8];
#pragma unroll
                for (int nt = 0; nt < 8; ++nt) {
                    const int tr = ch*64 + nt*8 + fr;
                    uint32_t bb[2];
                    bb[0] = *(const uint32_t*)&Bk[tr][kc];
                    bb[1] = *(const uint32_t*)&Bk[tr][kc + 8];
                    mma16816(sc[nt], a, bb);
                }
            }
        }

        uint32_t w0a = sMask[r0 + fr    ][2*ch], w0b = sMask[r0 + fr    ][2*ch + 1];
        uint32_t w1a = sMask[r0 + fr + 8][2*ch], w1b = sMask[r0 + fr + 8][2*ch + 1];
#pragma unroll
        for (int nt = 0; nt < 8; ++nt) {
            uint32_t wr0 = (nt < 4) ? w0a : w0b;
            uint32_t wr1 = (nt < 4) ? w1a : w1b;
            const int bbase = (nt & 3) * 8 + qc * 2;
            if (!((wr0 >> bbase) & 1))       sc[nt][0] = -1e30f;
            if (!((wr0 >> (bbase+1)) & 1))   sc[nt][1] = -1e30f;
            if (!((wr1 >> bbase) & 1))       sc[nt][2] = -1e30f;
            if (!((wr1 >> (bbase+1)) & 1))   sc[nt][3] = -1e30f;
        }

        float rx0 = -1e30f, rx1 = -1e30f;
#pragma unroll
        for (int nt = 0; nt < 8; ++nt) {
            rx0 = fmaxf(rx0, fmaxf(sc[nt][0], sc[nt][1]));
            rx1 = fmaxf(rx1, fmaxf(sc[nt][2], sc[nt][3]));
        }
#pragma unroll
        for (int o = 1; o <= 2; o <<= 1) {
            rx0 = fmaxf(rx0, __shfl_xor_sync(0xffffffffu, rx0, o));
            rx1 = fmaxf(rx1, __shfl_xor_sync(0xffffffffu, rx1, o));
        }
        const float mn0 = fmaxf(m0, rx0), mn1 = fmaxf(m1, rx1);
        const float al0 = __expf(m0 - mn0), al1 = __expf(m1 - mn1);
        const float z0 = (mn0 <= -1e29f) ? 0.f : 1.f;
        const float z1 = (mn1 <= -1e29f) ? 0.f : 1.f;
        float s0 = 0.f, s1 = 0.f;
#pragma unroll
        for (int nt = 0; nt < 8; ++nt) {
            sc[nt][0] = __expf(sc[nt][0] - mn0) * z0;
            sc[nt][1] = __expf(sc[nt][1] - mn0) * z0;
            sc[nt][2] = __expf(sc[nt][2] - mn1) * z1;
            sc[nt][3] = __expf(sc[nt][3] - mn1) * z1;
            s0 += sc[nt][0] + sc[nt][1];
            s1 += sc[nt][2] + sc[nt][3];
        }
#pragma unroll
        for (int o = 1; o <= 2; o <<= 1) {
            s0 += __shfl_xor_sync(0xffffffffu, s0, o);
            s1 += __shfl_xor_sync(0xffffffffu, s1, o);
        }
        l0 = l0 * al0 + s0;
        l1 = l1 * al1 + s1;
        m0 = mn0; m1 = mn1;
#pragma unroll
        for (int n = 0; n < 4; ++n) {
            Y[n][0] *= al0; Y[n][1] *= al0;
            Y[n][2] *= al1; Y[n][3] *= al1;
        }

        uint32_t ah[4][4], alo[4][4];
#pragma unroll
        for (int kt = 0; kt < 4; ++kt) {
            const int f0 = 2*kt, f1 = 2*kt + 1;
            ah[kt][0] = pack_bf2(sc[f0][0], sc[f0][1]);
            ah[kt][1] = pack_bf2(sc[f0][2], sc[f0][3]);
            ah[kt][2] = pack_bf2(sc[f1][0], sc[f1][1]);
            ah[kt][3] = pack_bf2(sc[f1][2], sc[f1][3]);
            alo[kt][0] = pack_bf2_res(sc[f0][0], sc[f0][1], ah[kt][0]);
            alo[kt][1] = pack_bf2_res(sc[f0][2], sc[f0][3], ah[kt][1]);
            alo[kt][2] = pack_bf2_res(sc[f1][0], sc[f1][1], ah[kt][2]);
            alo[kt][3] = pack_bf2_res(sc[f1][2], sc[f1][3], ah[kt][3]);
        }

#pragma unroll
        for (int term = 0; term < 3; ++term) {
            uint32_t (*Ap)[4] = (term == 1) ? alo : ah;
            __nv_bfloat16 (*Bv)[VTP] = (term == 2) ? sVTl : sVTh;
#pragma unroll
            for (int kt = 0; kt < 4; ++kt) {
#pragma unroll
                for (int nt = 0; nt < 4; ++nt) {
                    const int k0 = ch*64 + kt*16 + qc*2;
                    const int n  = nt*8 + fr;
                    uint32_t bb[2];
                    bb[0] = *(const uint32_t*)&Bv[n][k0];
                    bb[1] = *(const uint32_t*)&Bv[n][k0 + 8];
                    mma16816(Y[nt], Ap[kt], bb);
                }
            }
        }
    }

    float inv0 = (l0 > 0.f) ? 1.f / l0 : 0.f;
    float inv1 = (l1 > 0.f) ? 1.f / l1 : 0.f;
    if (l0 == 0.f) {
#pragma unroll
        for (int nt = 0; nt < 4; ++nt)
            for (int jj = 0; jj < 2; ++jj) {
                int col = nt*8 + qc*2 + jj;
                float s = 0.f;
                for (int t = 0; t < 256; ++t)
                    s += __bfloat162float(sVTh[col][t]) + __bfloat162float(sVTl[col][t]);
                Y[nt][jj] = s * (1.f/256.f);
            }
        inv0 = 1.f;
    }
    if (l1 == 0.f) {
#pragma unroll
        for (int nt = 0; nt < 4; ++nt)
            for (int jj = 0; jj < 2; ++jj) {
                int col = nt*8 + qc*2 + jj;
                float s = 0.f;
                for (int t = 0; t < 256; ++t)
                    s += __bfloat162float(sVTh[col][t]) + __bfloat162float(sVTl[col][t]);
                Y[nt][2 + jj] = s * (1.f/256.f);
            }
        inv1 = 1.f;
    }

    const int row0 = r0 + fr, row1 = r0 + fr + 8;
    const float* vx0 = g_vaux + ((size_t)(i*Bz + b)*T1c + row0) * Cc + h*32;
    const float* vx1 = g_vaux + ((size_t)(i*Bz + b)*T1c + row1) * Cc + h*32;
    __nv_bfloat16* y0 = d_y3 + (size_t)i*M1*K2_Y + (size_t)(b*T1c + row0)*K2_Y + h*32;
    __nv_bfloat16* y1 = d_y3 + (size_t)i*M1*K2_Y + (size_t)(b*T1c + row1)*K2_Y + h*32;
#pragma unroll
    for (int nt = 0; nt < 4; ++nt) {
        const int c0 = nt*8 + qc*2;
        float2 v0 = *(const float2*)(vx0 + c0);
        float2 v1 = *(const float2*)(vx1 + c0);
        float o00 = Y[nt][0]*inv0 + v0.x, o01 = Y[nt][1]*inv0 + v0.y;
        float o10 = Y[nt][2]*inv1 + v1.x, o11 = Y[nt][3]*inv1 + v1.y;
        uint32_t h0 = pack_bf2(o00, o01), l0p = pack_bf2_res(o00, o01, h0);
        uint32_t h1 = pack_bf2(o10, o11), l1p = pack_bf2_res(o10, o11, h1);
        *(uint32_t*)(y0 + c0)       = h0;
        *(uint32_t*)(y0 + 256 + c0) = l0p;
        *(uint32_t*)(y1 + c0)       = h1;
        *(uint32_t*)(y1 + 256 + c0) = l1p;
    }
}

// ---------------- final sum: 12 planes + biases ----------------
__global__ void sum_kernel(const float* __restrict__ bp, float* __restrict__ out)
{
    int e = blockIdx.x * 256 + threadIdx.x;
    int col4 = (e & 63) * 4;
    float4 o = make_float4(0.f, 0.f, 0.f, 0.f);
#pragma unroll
    for (int i = 0; i < NT; ++i) {
        float4 bi = *(const float4*)(bp + i*256 + col4);
        o.x += bi.x; o.y += bi.y; o.z += bi.z; o.w += bi.w;
#pragma unroll
        for (int s = 0; s < 4; ++s) {
            float4 pa = *(const float4*)(g_pp[s] + (size_t)i*M1*Cc + (size_t)e*4);
            o.x += pa.x; o.y += pa.y; o.z += pa.z; o.w += pa.w;
        }
    }
    *(float4*)(out + (size_t)e*4) = o;
}

// ---------------- launch ----------------
extern "C" void kernel_launch(void* const* d_in, const int* in_sizes, int n_in,
                              void* d_out, int out_size)
{
    const float* x1     = (const float*)d_in[0];
    const float* x2     = (const float*)d_in[1];
    const float* aux_x1 = (const float*)d_in[2];
    const float* aux_x2 = (const float*)d_in[3];
    const int*   masks  = (const int*)  d_in[4];
    const float* Wq     = (const float*)d_in[5];
    const float* bq     = (const float*)d_in[6];
    const float* Wk     = (const float*)d_in[7];
    const float* bk     = (const float*)d_in[8];
    const float* Wv     = (const float*)d_in[9];
    const float* bv     = (const float*)d_in[10];
    const float* Wp     = (const float*)d_in[11];
    const float* bp     = (const float*)d_in[12];
    float* out = (float*)d_out;

    cudaFuncSetAttribute(attn_flash_kernel,
                         cudaFuncAttributeMaxDynamicSharedMemorySize, ATTN_SMEM);
    cudaFuncSetAttribute(mma_qkv_kernel,
                         cudaFuncAttributeMaxDynamicSharedMemorySize, QKV_SMEM);
    cudaFuncSetAttribute(mma_proj_kernel,
                         cudaFuncAttributeMaxDynamicSharedMemorySize, PROJ_SMEM);

    prep_all_kernel<<<PREP_GRID, 256>>>(x1, x2, aux_x1, aux_x2, Wq, Wk, Wv, Wp, masks);
    mma_qkv_kernel<<<288, 256, QKV_SMEM>>>(bq, bk, bv);
    attn_flash_kernel<<<dim3(8, Bz, NT), 256, ATTN_SMEM>>>();
    mma_proj_kernel<<<384, 256, PROJ_SMEM>>>();
    sum_kernel<<<256, 256>>>(bp, out);
}

// round 16
// speedup vs baseline: 1.6560x; 1.0421x over previous
#include <cuda_runtime.h>
#include <cuda_bf16.h>
#include <cstdint>
#include <math.h>

#define NT 3
#define Bz 8
#define T1c 128
#define T2c 256
#define Cc 256
#define M1 (Bz*T1c)   /* 1024 */
#define M2 (Bz*T2c)   /* 2048 */

#define K3_Q   768
#define K3_KV  832
#define K3_AUX 64
#define K2_Y   512    /* y stored as [hi|lo] */

// ---------------- device scratch ----------------
__device__ __align__(16) __nv_bfloat16 d_x13 [M1 * K3_Q];
__device__ __align__(16) __nv_bfloat16 d_x2c3[M2 * K3_KV];
__device__ __align__(16) __nv_bfloat16 d_ax13[M1 * K3_AUX];
__device__ __align__(16) __nv_bfloat16 d_wq3 [NT * Cc * K3_Q];
__device__ __align__(16) __nv_bfloat16 d_wk3 [NT * Cc * K3_KV];
__device__ __align__(16) __nv_bfloat16 d_wv3 [NT * Cc * K3_KV];
__device__ __align__(16) __nv_bfloat16 d_wva3[NT * Cc * K3_AUX];
__device__ __align__(16) __nv_bfloat16 d_wp3 [NT * Cc * K3_Q];
__device__ __align__(16) __nv_bfloat16 d_y3  [NT * M1 * K2_Y];
__device__ __align__(16) __nv_bfloat16 d_qhi[NT*M1*Cc], d_qlo[NT*M1*Cc];
__device__ __align__(16) __nv_bfloat16 d_khi[NT*M2*Cc], d_klo[NT*M2*Cc];
__device__ __align__(16) __nv_bfloat16 d_vhi[NT*M2*Cc], d_vlo[NT*M2*Cc];
__device__ uint32_t d_maskp[NT*Bz*T1c*8];
__device__ float g_vaux[NT * M1 * Cc];
__device__ float g_pp[4][NT * M1 * Cc];

// ---------------- helpers ----------------
__device__ __forceinline__ uint32_t smem_u32(const void* p) {
    uint32_t a;
    asm("{ .reg .u64 t; cvta.to.shared.u64 t, %1; cvt.u32.u64 %0, t; }" : "=r"(a) : "l"(p));
    return a;
}
#define CP16(sm, gp) asm volatile("cp.async.cg.shared.global [%0], [%1], 16;" :: "r"(sm), "l"(gp))
#define CPC()  asm volatile("cp.async.commit_group;" ::: "memory")
#define CPW1() asm volatile("cp.async.wait_group 1;" ::: "memory")

__device__ __forceinline__ void mma16816(float* c, const uint32_t* a, const uint32_t* b) {
    asm volatile(
        "mma.sync.aligned.m16n8k16.row.col.f32.bf16.bf16.f32 "
        "{%0,%1,%2,%3}, {%4,%5,%6,%7}, {%8,%9}, {%0,%1,%2,%3};"
        : "+f"(c[0]), "+f"(c[1]), "+f"(c[2]), "+f"(c[3])
        : "r"(a[0]), "r"(a[1]), "r"(a[2]), "r"(a[3]), "r"(b[0]), "r"(b[1]));
}
__device__ __forceinline__ uint32_t pack_bf2(float x, float y) {
    __nv_bfloat162 t = __floats2bfloat162_rn(x, y);
    return *(uint32_t*)&t;
}
__device__ __forceinline__ uint32_t pack_bf2_res(float x, float y, uint32_t hi) {
    __nv_bfloat162 h = *(__nv_bfloat162*)&hi;
    return pack_bf2(x - __bfloat162float(h.x), y - __bfloat162float(h.y));
}

// ---------------- fused prep: inputs split + W split + maskpack -------------
#define N_X1 (M1*256)
#define N_X2 (M2*256)
#define N_A2 (M2*16)
#define N_A1 (M1*16)
#define PREP_TOT (N_X1 + N_X2 + N_A2 + N_A1)
#define PREP_BLKS (PREP_TOT/256)
#define PW_BLKS 804
#define MK_BLKS 384
#define PREP_GRID (PREP_BLKS + PW_BLKS + MK_BLKS)

__device__ void prep_inputs_dev(int blk, const float* __restrict__ x1, const float* __restrict__ x2,
                                const float* __restrict__ aux_x1, const float* __restrict__ aux_x2)
{
    int t = blk * 256 + threadIdx.x;
    float v; __nv_bfloat16* base; int o0, o1, o2;
    if (t < N_X1) {
        int m = t >> 8, k = t & 255;
        v = x1[t];
        base = d_x13 + (size_t)m * K3_Q;
        o0 = k; o1 = 256 + k; o2 = 512 + k;
    } else if (t < N_X1 + N_X2) {
        int e = t - N_X1, m = e >> 8, k = e & 255;
        v = x2[e];
        base = d_x2c3 + (size_t)m * K3_KV;
        o0 = k; o1 = 272 + k; o2 = 544 + k;
    } else if (t < N_X1 + N_X2 + N_A2) {
        int e = t - N_X1 - N_X2, m = e >> 4, k = e & 15;
        v = aux_x2[e];
        base = d_x2c3 + (size_t)m * K3_KV;
        o0 = 256 + k; o1 = 272 + 256 + k; o2 = 544 + 256 + k;
    } else {
        int e = t - N_X1 - N_X2 - N_A2, m = e >> 4, k = e & 15;
        v = aux_x1[e];
        base = d_ax13 + (size_t)m * K3_AUX;
        o0 = k; o1 = 16 + k; o2 = 32 + k;
    }
    __nv_bfloat16 hi = __float2bfloat16(v);
    __nv_bfloat16 lo = __float2bfloat16(v - __bfloat162float(hi));
    base[o0] = hi; base[o1] = lo; base[o2] = hi;
}

__device__ void prep_w_dev(int id, const float* __restrict__ Wq, const float* __restrict__ Wk,
                           const float* __restrict__ Wv, const float* __restrict__ Wp)
{
    __shared__ float sT[16][65];
    const float* src; __nv_bfloat16* dst; int Ksrc, K3pad, ktiles, rmode, srcRows, local;
    if (id < 192)      { local = id;       src = Wq; dst = d_wq3;  Ksrc = 256; K3pad = K3_Q;   ktiles = 16; rmode = 0; srcRows = 256; }
    else if (id < 396) { local = id - 192; src = Wk; dst = d_wk3;  Ksrc = 272; K3pad = K3_KV;  ktiles = 17; rmode = 1; srcRows = 288; }
    else if (id < 600) { local = id - 396; src = Wv; dst = d_wv3;  Ksrc = 272; K3pad = K3_KV;  ktiles = 17; rmode = 1; srcRows = 288; }
    else if (id < 612) { local = id - 600; src = Wv; dst = d_wva3; Ksrc = 16;  K3pad = K3_AUX; ktiles = 1;  rmode = 2; srcRows = 288; }
    else               { local = id - 612; src = Wp; dst = d_wp3;  Ksrc = 256; K3pad = K3_Q;   ktiles = 16; rmode = 0; srcRows = 256; }
    const int per = ktiles * 4;
    const int i = local / per, r = local % per;
    const int kb = (r >> 2) * 16, nb = (r & 3) * 64;
    const float* wb = src + (size_t)i * srcRows * 256;
    const int t = threadIdx.x;
#pragma unroll
    for (int rr = 0; rr < 4; ++rr) {
        int kk = rr * 4 + (t >> 6), nn = t & 63;
        int k = kb + kk;
        int row = (rmode == 0) ? k : ((rmode == 1) ? (k < 256 ? k : k + 16) : (256 + k));
        sT[kk][nn] = wb[(size_t)row * 256 + nb + nn];
    }
    __syncthreads();
#pragma unroll
    for (int rr = 0; rr < 4; ++rr) {
        int n2 = rr * 16 + (t >> 4), k2 = t & 15;
        float v = sT[k2][n2];
        __nv_bfloat16 hi = __float2bfloat16(v);
        __nv_bfloat16 lo = __float2bfloat16(v - __bfloat162float(hi));
        size_t base = (size_t)i * 256 * K3pad + (size_t)(nb + n2) * K3pad;
        int k = kb + k2;
        dst[base + k]            = hi;
        dst[base + Ksrc + k]     = hi;
        dst[base + 2 * Ksrc + k] = lo;
    }
}

__device__ void maskpack_dev(int blk, const int* __restrict__ masks)
{
    int row = blk * 8 + (threadIdx.x >> 5);
    int lane = threadIdx.x & 31;
    const int* mrow = masks + (size_t)row * 256;
#pragma unroll
    for (int j = 0; j < 8; ++j) {
        uint32_t w = __ballot_sync(0xffffffffu, mrow[j*32 + lane] != 0);
        if (lane == 0) d_maskp[row*8 + j] = w;
    }
}

__global__ __launch_bounds__(256)
void prep_all_kernel(const float* __restrict__ x1, const float* __restrict__ x2,
                     const float* __restrict__ aux_x1, const float* __restrict__ aux_x2,
                     const float* __restrict__ Wq, const float* __restrict__ Wk,
                     const float* __restrict__ Wv, const float* __restrict__ Wp,
                     const int* __restrict__ masks)
{
    const int id = blockIdx.x;
    if (id < PREP_BLKS)                 prep_inputs_dev(id, x1, x2, aux_x1, aux_x2);
    else if (id < PREP_BLKS + PW_BLKS)  prep_w_dev(id - PREP_BLKS, Wq, Wk, Wv, Wp);
    else                                maskpack_dev(id - PREP_BLKS - PW_BLKS, masks);
}

// ---------------- GEMM engine: (MI*32)x128 tile, K-chunk KCH, 3-stage -------
template<int MI, int KCH>
__device__ __forceinline__ void gemm_stage_load(
    char* stage, const __nv_bfloat16* __restrict__ A, int lda,
    const __nv_bfloat16* __restrict__ B, int ldb, int mb, int nb,
    int kofA, int kofB, int tid)
{
    const int GP = KCH + 8;
    const int CPR = KCH / 8;                 // CP16 per row
    __nv_bfloat16 (*sA)[GP] = (__nv_bfloat16(*)[GP])stage;
    __nv_bfloat16 (*sB)[GP] = (__nv_bfloat16(*)[GP])(stage + MI*32*GP*2);
#pragma unroll
    for (int j = 0; j < (MI*32*CPR)/256; ++j) {
        int idx = tid + j * 256;
        int row = idx / CPR, c8 = (idx % CPR) * 8;
        CP16(smem_u32(&sA[row][c8]), A + (size_t)(mb + row) * lda + kofA + c8);
    }
#pragma unroll
    for (int j = 0; j < (128*CPR)/256; ++j) {
        int idx = tid + j * 256;
        int row = idx / CPR, c8 = (idx % CPR) * 8;
        CP16(smem_u32(&sB[row][c8]), B + (size_t)(nb + row) * ldb + kofB + c8);
    }
}

template<int MI, int KCH, int REMAP_A>
__device__ __forceinline__ void mma_tile_run(
    const __nv_bfloat16* __restrict__ A, int lda,
    const __nv_bfloat16* __restrict__ B, int ldb,
    int NC, int chBase, float* __restrict__ outF,
    __nv_bfloat16* __restrict__ oHi, __nv_bfloat16* __restrict__ oLo, float scale,
    const float* __restrict__ bias, int mb, int nb)
{
    extern __shared__ __align__(16) char gsm[];
    const int GP = KCH + 8;
    const int STAGE = (MI*32 + 128) * GP * 2;
    float* sBias = (float*)(gsm + 3*STAGE);

    const int tid = threadIdx.x;
    const int wid = tid >> 5, lane = tid & 31;
    const int warpM = wid & 1, warpN = wid >> 1;
    const int fr = lane >> 2, qc = lane & 3;

    if (tid < 128) sBias[tid] = bias ? bias[nb + tid] : 0.f;

    float acc[MI][4][4];
#pragma unroll
    for (int mi = 0; mi < MI; ++mi)
#pragma unroll
        for (int ni = 0; ni < 4; ++ni)
#pragma unroll
            for (int q = 0; q < 4; ++q) acc[mi][ni][q] = 0.f;

    auto kA = [&](int g) { return (REMAP_A && g >= 512/KCH) ? (g - 512/KCH) * KCH : g * KCH; };

    gemm_stage_load<MI,KCH>(gsm, A, lda, B, ldb, mb, nb, kA(chBase), chBase*KCH, tid);
    CPC();
    if (NC > 1) gemm_stage_load<MI,KCH>(gsm + STAGE, A, lda, B, ldb, mb, nb,
                                        kA(chBase+1), (chBase+1)*KCH, tid);
    CPC();

    int st = 0, pf = 2;
    for (int ch = 0; ch < NC; ++ch) {
        CPW1();
        __syncthreads();
        if (ch + 2 < NC) {
            int g = chBase + ch + 2;
            gemm_stage_load<MI,KCH>(gsm + pf*STAGE, A, lda, B, ldb, mb, nb, kA(g), g*KCH, tid);
        }
        CPC();

        __nv_bfloat16 (*sA)[GP] = (__nv_bfloat16(*)[GP])(gsm + st*STAGE);
        __nv_bfloat16 (*sB)[GP] = (__nv_bfloat16(*)[GP])(gsm + st*STAGE + MI*32*GP*2);
#pragma unroll
        for (int kk = 0; kk < KCH/16; ++kk) {
            const int kc = kk * 16 + qc * 2;
            uint32_t a[MI][4], bb[4][2];
#pragma unroll
            for (int mi = 0; mi < MI; ++mi) {
                const int mr = warpM * (MI*16) + mi * 16 + fr;
                a[mi][0] = *(const uint32_t*)&sA[mr    ][kc];
                a[mi][1] = *(const uint32_t*)&sA[mr + 8][kc];
                a[mi][2] = *(const uint32_t*)&sA[mr    ][kc + 8];
                a[mi][3] = *(const uint32_t*)&sA[mr + 8][kc + 8];
            }
#pragma unroll
            for (int ni = 0; ni < 4; ++ni) {
                const int nr = warpN * 32 + ni * 8 + fr;
                bb[ni][0] = *(const uint32_t*)&sB[nr][kc];
                bb[ni][1] = *(const uint32_t*)&sB[nr][kc + 8];
            }
#pragma unroll
            for (int mi = 0; mi < MI; ++mi)
#pragma unroll
                for (int ni = 0; ni < 4; ++ni)
                    mma16816(acc[mi][ni], a[mi], bb[ni]);
        }
        st = (st == 2) ? 0 : st + 1;
        pf = (pf == 2) ? 0 : pf + 1;
    }

#pragma unroll
    for (int mi = 0; mi < MI; ++mi) {
        const int mr0 = mb + warpM * (MI*16) + mi * 16 + fr;
#pragma unroll
        for (int ni = 0; ni < 4; ++ni) {
            const int nloc = warpN * 32 + ni * 8 + qc * 2;
            const int ng = nb + nloc;
            float o00 = acc[mi][ni][0] + sBias[nloc];
            float o01 = acc[mi][ni][1] + sBias[nloc + 1];
            float o10 = acc[mi][ni][2] + sBias[nloc];
            float o11 = acc[mi][ni][3] + sBias[nloc + 1];
            if (outF) {
                *(float2*)(outF + (size_t)mr0 * Cc + ng)       = make_float2(o00, o01);
                *(float2*)(outF + (size_t)(mr0 + 8) * Cc + ng) = make_float2(o10, o11);
            } else {
                o00 *= scale; o01 *= scale; o10 *= scale; o11 *= scale;
                uint32_t h0 = pack_bf2(o00, o01), h1 = pack_bf2(o10, o11);
                uint32_t l0 = pack_bf2_res(o00, o01, h0), l1 = pack_bf2_res(o10, o11, h1);
                *(uint32_t*)(oHi + (size_t)mr0 * Cc + ng)       = h0;
                *(uint32_t*)(oHi + (size_t)(mr0 + 8) * Cc + ng) = h1;
                *(uint32_t*)(oLo + (size_t)mr0 * Cc + ng)       = l0;
                *(uint32_t*)(oLo + (size_t)(mr0 + 8) * Cc + ng) = l1;
            }
        }
    }
}

#define QKV_SMEM  (3*((128+128)*72*2) + 512)    /* 111104: KCH=64 */
#define PROJ_SMEM (3*((64+128)*40*2) + 512)     /* 46592:  KCH=32 */
#define QSCALE 0.17677669529663687f

// qkv fused (KCH=64): [0,48) q | [48,144) k | [144,240) v | [240,288) vaux
__global__ __launch_bounds__(256)
void mma_qkv_kernel(const float* __restrict__ bq, const float* __restrict__ bk,
                    const float* __restrict__ bv)
{
    const int id = blockIdx.x;
    if (id < 48) {
        int i = id / 16, r = id % 16, mt = r >> 1, nt = r & 1;
        mma_tile_run<4,64,0>(d_x13, K3_Q, d_wq3 + (size_t)i*Cc*K3_Q, K3_Q, 12, 0,
                             nullptr, d_qhi + (size_t)i*M1*Cc, d_qlo + (size_t)i*M1*Cc, QSCALE,
                             bq + i*Cc, mt*128, nt*128);
    } else if (id < 144) {
        int l = id - 48, i = l / 32, r = l % 32, mt = r >> 1, nt = r & 1;
        mma_tile_run<4,64,0>(d_x2c3, K3_KV, d_wk3 + (size_t)i*Cc*K3_KV, K3_KV, 13, 0,
                             nullptr, d_khi + (size_t)i*M2*Cc, d_klo + (size_t)i*M2*Cc, 1.f,
                             bk + i*Cc, mt*128, nt*128);
    } else if (id < 240) {
        int l = id - 144, i = l / 32, r = l % 32, mt = r >> 1, nt = r & 1;
        mma_tile_run<4,64,0>(d_x2c3, K3_KV, d_wv3 + (size_t)i*Cc*K3_KV, K3_KV, 13, 0,
                             nullptr, d_vhi + (size_t)i*M2*Cc, d_vlo + (size_t)i*M2*Cc, 1.f,
                             bv + i*Cc, mt*128, nt*128);
    } else {
        int l = id - 240, i = l / 16, r = l % 16, mt = r >> 1, nt = r & 1;
        mma_tile_run<4,64,0>(d_ax13, K3_AUX, d_wva3 + (size_t)i*Cc*K3_AUX, K3_AUX, 1, 0,
                             g_vaux + (size_t)i*M1*Cc, nullptr, nullptr, 1.f,
                             nullptr, mt*128, nt*128);
    }
}

// proj (KCH=32): 64x128 tiles, split-K 4-way, A [hi|lo] remap, grid 384
__global__ __launch_bounds__(256)
void mma_proj_kernel()
{
    const int id = blockIdx.x;
    const int s = id / 96;
    const int l = id % 96;
    int i = l / 32, r = l % 32, mt = r >> 1, nt = r & 1;
    float* outp = g_pp[s] + (size_t)i*M1*Cc;
    mma_tile_run<2,32,1>(d_y3 + (size_t)i*M1*K2_Y, K2_Y, d_wp3 + (size_t)i*Cc*K3_Q, K3_Q,
                         6, s*6, outp, nullptr, nullptr, 1.f,
                         nullptr, mt*64, nt*128);
}

// ---------------- flash attention, V transposed in smem ---------------------
#define APAD 40
#define VTP 264
#define OFF_QH 0
#define OFF_QL 10240
#define OFF_KH 20480
#define OFF_KL 40960
#define OFF_VTH 61440
#define OFF_VTL 78336
#define OFF_MK 95232
#define ATTN_SMEM 99328

__global__ __launch_bounds__(256)
void attn_flash_kernel()
{
    extern __shared__ __align__(16) char dsm[];
    __nv_bfloat16 (*sQh)[APAD] = (__nv_bfloat16(*)[APAD])(dsm + OFF_QH);
    __nv_bfloat16 (*sQl)[APAD] = (__nv_bfloat16(*)[APAD])(dsm + OFF_QL);
    __nv_bfloat16 (*sKh)[APAD] = (__nv_bfloat16(*)[APAD])(dsm + OFF_KH);
    __nv_bfloat16 (*sKl)[APAD] = (__nv_bfloat16(*)[APAD])(dsm + OFF_KL);
    __nv_bfloat16 (*sVTh)[VTP] = (__nv_bfloat16(*)[VTP])(dsm + OFF_VTH);
    __nv_bfloat16 (*sVTl)[VTP] = (__nv_bfloat16(*)[VTP])(dsm + OFF_VTL);
    uint32_t (*sMask)[8] = (uint32_t(*)[8])(dsm + OFF_MK);

    const int h = blockIdx.x, b = blockIdx.y, i = blockIdx.z;
    const int tid = threadIdx.x;
    const int warp = tid >> 5, lane = tid & 31;
    const int fr = lane >> 2, qc = lane & 3;
    const int r0 = warp * 16;

    const size_t qoff = ((size_t)(i*Bz + b) * T1c) * Cc + h*32;
    const size_t koff = ((size_t)(i*Bz + b) * T2c) * Cc + h*32;

#pragma unroll
    for (int j = 0; j < 2; ++j) {
        int idx = tid + j * 256;
        int row = idx >> 2, c8 = (idx & 3) * 8;
        *(float4*)&sQh[row][c8] = *(const float4*)(d_qhi + qoff + (size_t)row*Cc + c8);
        *(float4*)&sQl[row][c8] = *(const float4*)(d_qlo + qoff + (size_t)row*Cc + c8);
    }
#pragma unroll
    for (int j = 0; j < 4; ++j) {
        int idx = tid + j * 256;
        int row = idx >> 2, c8 = (idx & 3) * 8;
        *(float4*)&sKh[row][c8] = *(const float4*)(d_khi + koff + (size_t)row*Cc + c8);
        *(float4*)&sKl[row][c8] = *(const float4*)(d_klo + koff + (size_t)row*Cc + c8);
        float4 vh4 = *(const float4*)(d_vhi + koff + (size_t)row*Cc + c8);
        float4 vl4 = *(const float4*)(d_vlo + koff + (size_t)row*Cc + c8);
        const __nv_bfloat16* vh = (const __nv_bfloat16*)&vh4;
        const __nv_bfloat16* vl = (const __nv_bfloat16*)&vl4;
#pragma unroll
        for (int jj = 0; jj < 8; ++jj) {
            sVTh[c8 + jj][row] = vh[jj];
            sVTl[c8 + jj][row] = vl[jj];
        }
    }
#pragma unroll
    for (int j = 0; j < 4; ++j) {
        int w = tid + j * 256;
        ((uint32_t*)(dsm + OFF_MK))[w] = d_maskp[(size_t)(i*Bz + b)*1024 + w];
    }
    __syncthreads();

    float m0 = -1e30f, m1 = -1e30f, l0 = 0.f, l1 = 0.f;
    float Y[4][4];
#pragma unroll
    for (int n = 0; n < 4; ++n)
#pragma unroll
        for (int q = 0; q < 4; ++q) Y[n][q] = 0.f;

    for (int ch = 0; ch < 4; ++ch) {
        float sc[8][4];
#pragma unroll
        for (int n = 0; n < 8; ++n)
#pragma unroll
            for (int q = 0; q < 4; ++q) sc[n][q] = 0.f;

#pragma unroll
        for (int term = 0; term < 3; ++term) {
            __nv_bfloat16 (*Aq)[APAD] = (term == 1) ? sQl : sQh;
            __nv_bfloat16 (*Bk)[APAD] = (term == 2) ? sKl : sKh;
#pragma unroll
            for (int kk = 0; kk < 2; ++kk) {
                const int kc = kk * 16 + qc * 2;
                uint32_t a[4];
                a[0] = *(const uint32_t*)&Aq[r0 + fr    ][kc];
                a[1] = *(const uint32_t*)&Aq[r0 + fr + 8][kc];
                a[2] = *(const uint32_t*)&Aq[r0 + fr    ][kc + 8];
                a[3] = *(const uint32_t*)&Aq[r0 + fr + 8][kc + 8];
#pragma unroll
                for (int nt = 0; nt < 8; ++nt) {
                    const int tr = ch*64 + nt*8 + fr;
                    uint32_t bb[2];
                    bb[0] = *(const uint32_t*)&Bk[tr][kc];
                    bb[1] = *(const uint32_t*)&Bk[tr][kc + 8];
                    mma16816(sc[nt], a, bb);
                }
            }
        }

        uint32_t w0a = sMask[r0 + fr    ][2*ch], w0b = sMask[r0 + fr    ][2*ch + 1];
        uint32_t w1a = sMask[r0 + fr + 8][2*ch], w1b = sMask[r0 + fr + 8][2*ch + 1];
#pragma unroll
        for (int nt = 0; nt < 8; ++nt) {
            uint32_t wr0 = (nt < 4) ? w0a : w0b;
            uint32_t wr1 = (nt < 4) ? w1a : w1b;
            const int bbase = (nt & 3) * 8 + qc * 2;
            if (!((wr0 >> bbase) & 1))       sc[nt][0] = -1e30f;
            if (!((wr0 >> (bbase+1)) & 1))   sc[nt][1] = -1e30f;
            if (!((wr1 >> bbase) & 1))       sc[nt][2] = -1e30f;
            if (!((wr1 >> (bbase+1)) & 1))   sc[nt][3] = -1e30f;
        }

        float rx0 = -1e30f, rx1 = -1e30f;
#pragma unroll
        for (int nt = 0; nt < 8; ++nt) {
            rx0 = fmaxf(rx0, fmaxf(sc[nt][0], sc[nt][1]));
            rx1 = fmaxf(rx1, fmaxf(sc[nt][2], sc[nt][3]));
        }
#pragma unroll
        for (int o = 1; o <= 2; o <<= 1) {
            rx0 = fmaxf(rx0, __shfl_xor_sync(0xffffffffu, rx0, o));
            rx1 = fmaxf(rx1, __shfl_xor_sync(0xffffffffu, rx1, o));
        }
        const float mn0 = fmaxf(m0, rx0), mn1 = fmaxf(m1, rx1);
        const float al0 = __expf(m0 - mn0), al1 = __expf(m1 - mn1);
        const float z0 = (mn0 <= -1e29f) ? 0.f : 1.f;
        const float z1 = (mn1 <= -1e29f) ? 0.f : 1.f;
        float s0 = 0.f, s1 = 0.f;
#pragma unroll
        for (int nt = 0; nt < 8; ++nt) {
            sc[nt][0] = __expf(sc[nt][0] - mn0) * z0;
            sc[nt][1] = __expf(sc[nt][1] - mn0) * z0;
            sc[nt][2] = __expf(sc[nt][2] - mn1) * z1;
            sc[nt][3] = __expf(sc[nt][3] - mn1) * z1;
            s0 += sc[nt][0] + sc[nt][1];
            s1 += sc[nt][2] + sc[nt][3];
        }
#pragma unroll
        for (int o = 1; o <= 2; o <<= 1) {
            s0 += __shfl_xor_sync(0xffffffffu, s0, o);
            s1 += __shfl_xor_sync(0xffffffffu, s1, o);
        }
        l0 = l0 * al0 + s0;
        l1 = l1 * al1 + s1;
        m0 = mn0; m1 = mn1;
#pragma unroll
        for (int n = 0; n < 4; ++n) {
            Y[n][0] *= al0; Y[n][1] *= al0;
            Y[n][2] *= al1; Y[n][3] *= al1;
        }

        uint32_t ah[4][4], alo[4][4];
#pragma unroll
        for (int kt = 0; kt < 4; ++kt) {
            const int f0 = 2*kt, f1 = 2*kt + 1;
            ah[kt][0] = pack_bf2(sc[f0][0], sc[f0][1]);
            ah[kt][1] = pack_bf2(sc[f0][2], sc[f0][3]);
            ah[kt][2] = pack_bf2(sc[f1][0], sc[f1][1]);
            ah[kt][3] = pack_bf2(sc[f1][2], sc[f1][3]);
            alo[kt][0] = pack_bf2_res(sc[f0][0], sc[f0][1], ah[kt][0]);
            alo[kt][1] = pack_bf2_res(sc[f0][2], sc[f0][3], ah[kt][1]);
            alo[kt][2] = pack_bf2_res(sc[f1][0], sc[f1][1], ah[kt][2]);
            alo[kt][3] = pack_bf2_res(sc[f1][2], sc[f1][3], ah[kt][3]);
        }

#pragma unroll
        for (int term = 0; term < 3; ++term) {
            uint32_t (*Ap)[4] = (term == 1) ? alo : ah;
            __nv_bfloat16 (*Bv)[VTP] = (term == 2) ? sVTl : sVTh;
#pragma unroll
            for (int kt = 0; kt < 4; ++kt) {
#pragma unroll
                for (int nt = 0; nt < 4; ++nt) {
                    const int k0 = ch*64 + kt*16 + qc*2;
                    const int n  = nt*8 + fr;
                    uint32_t bb[2];
                    bb[0] = *(const uint32_t*)&Bv[n][k0];
                    bb[1] = *(const uint32_t*)&Bv[n][k0 + 8];
                    mma16816(Y[nt], Ap[kt], bb);
                }
            }
        }
    }

    float inv0 = (l0 > 0.f) ? 1.f / l0 : 0.f;
    float inv1 = (l1 > 0.f) ? 1.f / l1 : 0.f;
    if (l0 == 0.f) {
#pragma unroll
        for (int nt = 0; nt < 4; ++nt)
            for (int jj = 0; jj < 2; ++jj) {
                int col = nt*8 + qc*2 + jj;
                float s = 0.f;
                for (int t = 0; t < 256; ++t)
                    s += __bfloat162float(sVTh[col][t]) + __bfloat162float(sVTl[col][t]);
                Y[nt][jj] = s * (1.f/256.f);
            }
        inv0 = 1.f;
    }
    if (l1 == 0.f) {
#pragma unroll
        for (int nt = 0; nt < 4; ++nt)
            for (int jj = 0; jj < 2; ++jj) {
                int col = nt*8 + qc*2 + jj;
                float s = 0.f;
                for (int t = 0; t < 256; ++t)
                    s += __bfloat162float(sVTh[col][t]) + __bfloat162float(sVTl[col][t]);
                Y[nt][2 + jj] = s * (1.f/256.f);
            }
        inv1 = 1.f;
    }

    const int row0 = r0 + fr, row1 = r0 + fr + 8;
    const float* vx0 = g_vaux + ((size_t)(i*Bz + b)*T1c + row0) * Cc + h*32;
    const float* vx1 = g_vaux + ((size_t)(i*Bz + b)*T1c + row1) * Cc + h*32;
    __nv_bfloat16* y0 = d_y3 + (size_t)i*M1*K2_Y + (size_t)(b*T1c + row0)*K2_Y + h*32;
    __nv_bfloat16* y1 = d_y3 + (size_t)i*M1*K2_Y + (size_t)(b*T1c + row1)*K2_Y + h*32;
#pragma unroll
    for (int nt = 0; nt < 4; ++nt) {
        const int c0 = nt*8 + qc*2;
        float2 v0 = *(const float2*)(vx0 + c0);
        float2 v1 = *(const float2*)(vx1 + c0);
        float o00 = Y[nt][0]*inv0 + v0.x, o01 = Y[nt][1]*inv0 + v0.y;
        float o10 = Y[nt][2]*inv1 + v1.x, o11 = Y[nt][3]*inv1 + v1.y;
        uint32_t h0 = pack_bf2(o00, o01), l0p = pack_bf2_res(o00, o01, h0);
        uint32_t h1 = pack_bf2(o10, o11), l1p = pack_bf2_res(o10, o11, h1);
        *(uint32_t*)(y0 + c0)       = h0;
        *(uint32_t*)(y0 + 256 + c0) = l0p;
        *(uint32_t*)(y1 + c0)       = h1;
        *(uint32_t*)(y1 + 256 + c0) = l1p;
    }
}

// ---------------- final sum: 12 planes + biases ----------------
__global__ void sum_kernel(const float* __restrict__ bp, float* __restrict__ out)
{
    int e = blockIdx.x * 256 + threadIdx.x;
    int col4 = (e & 63) * 4;
    float4 o = make_float4(0.f, 0.f, 0.f, 0.f);
#pragma unroll
    for (int i = 0; i < NT; ++i) {
        float4 bi = *(const float4*)(bp + i*256 + col4);
        o.x += bi.x; o.y += bi.y; o.z += bi.z; o.w += bi.w;
#pragma unroll
        for (int s = 0; s < 4; ++s) {
            float4 pa = *(const float4*)(g_pp[s] + (size_t)i*M1*Cc + (size_t)e*4);
            o.x += pa.x; o.y += pa.y; o.z += pa.z; o.w += pa.w;
        }
    }
    *(float4*)(out + (size_t)e*4) = o;
}

// ---------------- launch ----------------
extern "C" void kernel_launch(void* const* d_in, const int* in_sizes, int n_in,
                              void* d_out, int out_size)
{
    const float* x1     = (const float*)d_in[0];
    const float* x2     = (const float*)d_in[1];
    const float* aux_x1 = (const float*)d_in[2];
    const float* aux_x2 = (const float*)d_in[3];
    const int*   masks  = (const int*)  d_in[4];
    const float* Wq     = (const float*)d_in[5];
    const float* bq     = (const float*)d_in[6];
    const float* Wk     = (const float*)d_in[7];
    const float* bk     = (const float*)d_in[8];
    const float* Wv     = (const float*)d_in[9];
    const float* bv     = (const float*)d_in[10];
    const float* Wp     = (const float*)d_in[11];
    const float* bp     = (const float*)d_in[12];
    float* out = (float*)d_out;

    cudaFuncSetAttribute(attn_flash_kernel,
                         cudaFuncAttributeMaxDynamicSharedMemorySize, ATTN_SMEM);
    cudaFuncSetAttribute(mma_qkv_kernel,
                         cudaFuncAttributeMaxDynamicSharedMemorySize, QKV_SMEM);
    cudaFuncSetAttribute(mma_proj_kernel,
                         cudaFuncAttributeMaxDynamicSharedMemorySize, PROJ_SMEM);

    prep_all_kernel<<<PREP_GRID, 256>>>(x1, x2, aux_x1, aux_x2, Wq, Wk, Wv, Wp, masks);
    mma_qkv_kernel<<<288, 256, QKV_SMEM>>>(bq, bk, bv);
    attn_flash_kernel<<<dim3(8, Bz, NT), 256, ATTN_SMEM>>>();
    mma_proj_kernel<<<384, 256, PROJ_SMEM>>>();
    sum_kernel<<<256, 256>>>(bp, out);
}

// round 17
// speedup vs baseline: 1.7153x; 1.0358x over previous
#include <cuda_runtime.h>
#include <cuda_bf16.h>
#include <cstdint>
#include <math.h>

#define NT 3
#define Bz 8
#define T1c 128
#define T2c 256
#define Cc 256
#define M1 (Bz*T1c)   /* 1024 */
#define M2 (Bz*T2c)   /* 2048 */

#define K3_Q   768
#define K3_KV  832
#define K3_AUX 64
#define K2_Y   512    /* y stored as [hi|lo] */

// ---------------- device scratch ----------------
__device__ __align__(16) __nv_bfloat16 d_x13 [M1 * K3_Q];
__device__ __align__(16) __nv_bfloat16 d_x2c3[M2 * K3_KV];
__device__ __align__(16) __nv_bfloat16 d_ax13[M1 * K3_AUX];
__device__ __align__(16) __nv_bfloat16 d_wq3 [NT * Cc * K3_Q];
__device__ __align__(16) __nv_bfloat16 d_wk3 [NT * Cc * K3_KV];
__device__ __align__(16) __nv_bfloat16 d_wv3 [NT * Cc * K3_KV];
__device__ __align__(16) __nv_bfloat16 d_wva3[NT * Cc * K3_AUX];
__device__ __align__(16) __nv_bfloat16 d_wp3 [NT * Cc * K3_Q];
__device__ __align__(16) __nv_bfloat16 d_y3  [NT * M1 * K2_Y];
__device__ __align__(16) __nv_bfloat16 d_qhi[NT*M1*Cc], d_qlo[NT*M1*Cc];
__device__ __align__(16) __nv_bfloat16 d_khi[NT*M2*Cc], d_klo[NT*M2*Cc];
__device__ __align__(16) __nv_bfloat16 d_vhi[NT*M2*Cc], d_vlo[NT*M2*Cc];
__device__ uint32_t d_maskp[NT*Bz*T1c*8];
__device__ float g_vaux[NT * M1 * Cc];
__device__ float g_pp[4][NT * M1 * Cc];

// ---------------- helpers ----------------
__device__ __forceinline__ uint32_t smem_u32(const void* p) {
    uint32_t a;
    asm("{ .reg .u64 t; cvta.to.shared.u64 t, %1; cvt.u32.u64 %0, t; }" : "=r"(a) : "l"(p));
    return a;
}
#define CP16(sm, gp) asm volatile("cp.async.cg.shared.global [%0], [%1], 16;" :: "r"(sm), "l"(gp))
#define CPC()  asm volatile("cp.async.commit_group;" ::: "memory")
#define CPW1() asm volatile("cp.async.wait_group 1;" ::: "memory")

__device__ __forceinline__ void mma16816(float* c, const uint32_t* a, const uint32_t* b) {
    asm volatile(
        "mma.sync.aligned.m16n8k16.row.col.f32.bf16.bf16.f32 "
        "{%0,%1,%2,%3}, {%4,%5,%6,%7}, {%8,%9}, {%0,%1,%2,%3};"
        : "+f"(c[0]), "+f"(c[1]), "+f"(c[2]), "+f"(c[3])
        : "r"(a[0]), "r"(a[1]), "r"(a[2]), "r"(a[3]), "r"(b[0]), "r"(b[1]));
}
__device__ __forceinline__ uint32_t pack_bf2(float x, float y) {
    __nv_bfloat162 t = __floats2bfloat162_rn(x, y);
    return *(uint32_t*)&t;
}
__device__ __forceinline__ uint32_t pack_bf2_res(float x, float y, uint32_t hi) {
    __nv_bfloat162 h = *(__nv_bfloat162*)&hi;
    return pack_bf2(x - __bfloat162float(h.x), y - __bfloat162float(h.y));
}

// ---------------- fused prep: inputs split (x4) + W split + maskpack --------
#define N_X1 (M1*256)
#define N_X2 (M2*256)
#define N_A2 (M2*16)
#define N_A1 (M1*16)
#define PREP_TOT (N_X1 + N_X2 + N_A2 + N_A1)
#define PREP_BLKS (PREP_TOT/1024)       /* 816: 4 elems/thread */
#define PW_BLKS 804
#define MK_BLKS 384
#define PREP_GRID (PREP_BLKS + PW_BLKS + MK_BLKS)

__device__ void prep_inputs_dev(int blk, const float* __restrict__ x1, const float* __restrict__ x2,
                                const float* __restrict__ aux_x1, const float* __restrict__ aux_x2)
{
    int t = blk * 256 + threadIdx.x;     // quad index
    const float* src; __nv_bfloat16* base; int o0, o1, o2;
    if (t < N_X1/4) {
        int e = t * 4, m = e >> 8, k = e & 255;
        src = x1 + e;
        base = d_x13 + (size_t)m * K3_Q;
        o0 = k; o1 = 256 + k; o2 = 512 + k;
    } else if (t < (N_X1 + N_X2)/4) {
        int e = t * 4 - N_X1, m = e >> 8, k = e & 255;
        src = x2 + e;
        base = d_x2c3 + (size_t)m * K3_KV;
        o0 = k; o1 = 272 + k; o2 = 544 + k;
    } else if (t < (N_X1 + N_X2 + N_A2)/4) {
        int e = t * 4 - N_X1 - N_X2, m = e >> 4, k = e & 15;
        src = aux_x2 + e;
        base = d_x2c3 + (size_t)m * K3_KV;
        o0 = 256 + k; o1 = 528 + k; o2 = 800 + k;
    } else {
        int e = t * 4 - N_X1 - N_X2 - N_A2, m = e >> 4, k = e & 15;
        src = aux_x1 + e;
        base = d_ax13 + (size_t)m * K3_AUX;
        o0 = k; o1 = 16 + k; o2 = 32 + k;
    }
    float4 v = *(const float4*)src;
    uint32_t h01 = pack_bf2(v.x, v.y);
    uint32_t h23 = pack_bf2(v.z, v.w);
    uint32_t l01 = pack_bf2_res(v.x, v.y, h01);
    uint32_t l23 = pack_bf2_res(v.z, v.w, h23);
    uint2 hv = make_uint2(h01, h23);
    uint2 lv = make_uint2(l01, l23);
    *(uint2*)(base + o0) = hv;
    *(uint2*)(base + o1) = lv;
    *(uint2*)(base + o2) = hv;
}

__device__ void prep_w_dev(int id, const float* __restrict__ Wq, const float* __restrict__ Wk,
                           const float* __restrict__ Wv, const float* __restrict__ Wp)
{
    __shared__ float sT[16][65];
    const float* src; __nv_bfloat16* dst; int Ksrc, K3pad, ktiles, rmode, srcRows, local;
    if (id < 192)      { local = id;       src = Wq; dst = d_wq3;  Ksrc = 256; K3pad = K3_Q;   ktiles = 16; rmode = 0; srcRows = 256; }
    else if (id < 396) { local = id - 192; src = Wk; dst = d_wk3;  Ksrc = 272; K3pad = K3_KV;  ktiles = 17; rmode = 1; srcRows = 288; }
    else if (id < 600) { local = id - 396; src = Wv; dst = d_wv3;  Ksrc = 272; K3pad = K3_KV;  ktiles = 17; rmode = 1; srcRows = 288; }
    else if (id < 612) { local = id - 600; src = Wv; dst = d_wva3; Ksrc = 16;  K3pad = K3_AUX; ktiles = 1;  rmode = 2; srcRows = 288; }
    else               { local = id - 612; src = Wp; dst = d_wp3;  Ksrc = 256; K3pad = K3_Q;   ktiles = 16; rmode = 0; srcRows = 256; }
    const int per = ktiles * 4;
    const int i = local / per, r = local % per;
    const int kb = (r >> 2) * 16, nb = (r & 3) * 64;
    const float* wb = src + (size_t)i * srcRows * 256;
    const int t = threadIdx.x;
#pragma unroll
    for (int rr = 0; rr < 4; ++rr) {
        int kk = rr * 4 + (t >> 6), nn = t & 63;
        int k = kb + kk;
        int row = (rmode == 0) ? k : ((rmode == 1) ? (k < 256 ? k : k + 16) : (256 + k));
        sT[kk][nn] = wb[(size_t)row * 256 + nb + nn];
    }
    __syncthreads();
#pragma unroll
    for (int rr = 0; rr < 4; ++rr) {
        int n2 = rr * 16 + (t >> 4), k2 = t & 15;
        float v = sT[k2][n2];
        __nv_bfloat16 hi = __float2bfloat16(v);
        __nv_bfloat16 lo = __float2bfloat16(v - __bfloat162float(hi));
        size_t base = (size_t)i * 256 * K3pad + (size_t)(nb + n2) * K3pad;
        int k = kb + k2;
        dst[base + k]            = hi;
        dst[base + Ksrc + k]     = hi;
        dst[base + 2 * Ksrc + k] = lo;
    }
}

__device__ void maskpack_dev(int blk, const int* __restrict__ masks)
{
    int row = blk * 8 + (threadIdx.x >> 5);
    int lane = threadIdx.x & 31;
    const int* mrow = masks + (size_t)row * 256;
#pragma unroll
    for (int j = 0; j < 8; ++j) {
        uint32_t w = __ballot_sync(0xffffffffu, mrow[j*32 + lane] != 0);
        if (lane == 0) d_maskp[row*8 + j] = w;
    }
}

__global__ __launch_bounds__(256)
void prep_all_kernel(const float* __restrict__ x1, const float* __restrict__ x2,
                     const float* __restrict__ aux_x1, const float* __restrict__ aux_x2,
                     const float* __restrict__ Wq, const float* __restrict__ Wk,
                     const float* __restrict__ Wv, const float* __restrict__ Wp,
                     const int* __restrict__ masks)
{
    const int id = blockIdx.x;
    if (id < PREP_BLKS)                 prep_inputs_dev(id, x1, x2, aux_x1, aux_x2);
    else if (id < PREP_BLKS + PW_BLKS)  prep_w_dev(id - PREP_BLKS, Wq, Wk, Wv, Wp);
    else                                maskpack_dev(id - PREP_BLKS - PW_BLKS, masks);
}

// ---------------- GEMM engine: (MI*32)x128 tile, K-chunk KCH, 3-stage -------
template<int MI, int KCH>
__device__ __forceinline__ void gemm_stage_load(
    char* stage, const __nv_bfloat16* __restrict__ A, int lda,
    const __nv_bfloat16* __restrict__ B, int ldb, int mb, int nb,
    int kofA, int kofB, int tid)
{
    const int GP = KCH + 8;
    const int CPR = KCH / 8;
    __nv_bfloat16 (*sA)[GP] = (__nv_bfloat16(*)[GP])stage;
    __nv_bfloat16 (*sB)[GP] = (__nv_bfloat16(*)[GP])(stage + MI*32*GP*2);
#pragma unroll
    for (int j = 0; j < (MI*32*CPR)/256; ++j) {
        int idx = tid + j * 256;
        int row = idx / CPR, c8 = (idx % CPR) * 8;
        CP16(smem_u32(&sA[row][c8]), A + (size_t)(mb + row) * lda + kofA + c8);
    }
#pragma unroll
    for (int j = 0; j < (128*CPR)/256; ++j) {
        int idx = tid + j * 256;
        int row = idx / CPR, c8 = (idx % CPR) * 8;
        CP16(smem_u32(&sB[row][c8]), B + (size_t)(nb + row) * ldb + kofB + c8);
    }
}

template<int MI, int KCH, int REMAP_A>
__device__ __forceinline__ void mma_tile_run(
    const __nv_bfloat16* __restrict__ A, int lda,
    const __nv_bfloat16* __restrict__ B, int ldb,
    int NC, int chBase, float* __restrict__ outF,
    __nv_bfloat16* __restrict__ oHi, __nv_bfloat16* __restrict__ oLo, float scale,
    const float* __restrict__ bias, int mb, int nb)
{
    extern __shared__ __align__(16) char gsm[];
    const int GP = KCH + 8;
    const int STAGE = (MI*32 + 128) * GP * 2;
    float* sBias = (float*)(gsm + 3*STAGE);

    const int tid = threadIdx.x;
    const int wid = tid >> 5, lane = tid & 31;
    const int warpM = wid & 1, warpN = wid >> 1;
    const int fr = lane >> 2, qc = lane & 3;

    if (tid < 128) sBias[tid] = bias ? bias[nb + tid] : 0.f;

    float acc[MI][4][4];
#pragma unroll
    for (int mi = 0; mi < MI; ++mi)
#pragma unroll
        for (int ni = 0; ni < 4; ++ni)
#pragma unroll
            for (int q = 0; q < 4; ++q) acc[mi][ni][q] = 0.f;

    auto kA = [&](int g) { return (REMAP_A && g >= 512/KCH) ? (g - 512/KCH) * KCH : g * KCH; };

    gemm_stage_load<MI,KCH>(gsm, A, lda, B, ldb, mb, nb, kA(chBase), chBase*KCH, tid);
    CPC();
    if (NC > 1) gemm_stage_load<MI,KCH>(gsm + STAGE, A, lda, B, ldb, mb, nb,
                                        kA(chBase+1), (chBase+1)*KCH, tid);
    CPC();

    int st = 0, pf = 2;
    for (int ch = 0; ch < NC; ++ch) {
        CPW1();
        __syncthreads();
        if (ch + 2 < NC) {
            int g = chBase + ch + 2;
            gemm_stage_load<MI,KCH>(gsm + pf*STAGE, A, lda, B, ldb, mb, nb, kA(g), g*KCH, tid);
        }
        CPC();

        __nv_bfloat16 (*sA)[GP] = (__nv_bfloat16(*)[GP])(gsm + st*STAGE);
        __nv_bfloat16 (*sB)[GP] = (__nv_bfloat16(*)[GP])(gsm + st*STAGE + MI*32*GP*2);
#pragma unroll
        for (int kk = 0; kk < KCH/16; ++kk) {
            const int kc = kk * 16 + qc * 2;
            uint32_t a[MI][4], bb[4][2];
#pragma unroll
            for (int mi = 0; mi < MI; ++mi) {
                const int mr = warpM * (MI*16) + mi * 16 + fr;
                a[mi][0] = *(const uint32_t*)&sA[mr    ][kc];
                a[mi][1] = *(const uint32_t*)&sA[mr + 8][kc];
                a[mi][2] = *(const uint32_t*)&sA[mr    ][kc + 8];
                a[mi][3] = *(const uint32_t*)&sA[mr + 8][kc + 8];
            }
#pragma unroll
            for (int ni = 0; ni < 4; ++ni) {
                const int nr = warpN * 32 + ni * 8 + fr;
                bb[ni][0] = *(const uint32_t*)&sB[nr][kc];
                bb[ni][1] = *(const uint32_t*)&sB[nr][kc + 8];
            }
#pragma unroll
            for (int mi = 0; mi < MI; ++mi)
#pragma unroll
                for (int ni = 0; ni < 4; ++ni)
                    mma16816(acc[mi][ni], a[mi], bb[ni]);
        }
        st = (st == 2) ? 0 : st + 1;
        pf = (pf == 2) ? 0 : pf + 1;
    }

#pragma unroll
    for (int mi = 0; mi < MI; ++mi) {
        const int mr0 = mb + warpM * (MI*16) + mi * 16 + fr;
#pragma unroll
        for (int ni = 0; ni < 4; ++ni) {
            const int nloc = warpN * 32 + ni * 8 + qc * 2;
            const int ng = nb + nloc;
            float o00 = acc[mi][ni][0] + sBias[nloc];
            float o01 = acc[mi][ni][1] + sBias[nloc + 1];
            float o10 = acc[mi][ni][2] + sBias[nloc];
            float o11 = acc[mi][ni][3] + sBias[nloc + 1];
            if (outF) {
                *(float2*)(outF + (size_t)mr0 * Cc + ng)       = make_float2(o00, o01);
                *(float2*)(outF + (size_t)(mr0 + 8) * Cc + ng) = make_float2(o10, o11);
            } else {
                o00 *= scale; o01 *= scale; o10 *= scale; o11 *= scale;
                uint32_t h0 = pack_bf2(o00, o01), h1 = pack_bf2(o10, o11);
                uint32_t l0 = pack_bf2_res(o00, o01, h0), l1 = pack_bf2_res(o10, o11, h1);
                *(uint32_t*)(oHi + (size_t)mr0 * Cc + ng)       = h0;
                *(uint32_t*)(oHi + (size_t)(mr0 + 8) * Cc + ng) = h1;
                *(uint32_t*)(oLo + (size_t)mr0 * Cc + ng)       = l0;
                *(uint32_t*)(oLo + (size_t)(mr0 + 8) * Cc + ng) = l1;
            }
        }
    }
}

#define QKV_SMEM  (3*((128+128)*72*2) + 512)    /* 111104: KCH=64 */
#define PROJ_SMEM (3*((64+128)*72*2) + 512)     /* 83456:  KCH=64 */
#define QSCALE 0.17677669529663687f

// qkv fused (KCH=64): [0,48) q | [48,144) k | [144,240) v | [240,288) vaux
__global__ __launch_bounds__(256)
void mma_qkv_kernel(const float* __restrict__ bq, const float* __restrict__ bk,
                    const float* __restrict__ bv)
{
    const int id = blockIdx.x;
    if (id < 48) {
        int i = id / 16, r = id % 16, mt = r >> 1, nt = r & 1;
        mma_tile_run<4,64,0>(d_x13, K3_Q, d_wq3 + (size_t)i*Cc*K3_Q, K3_Q, 12, 0,
                             nullptr, d_qhi + (size_t)i*M1*Cc, d_qlo + (size_t)i*M1*Cc, QSCALE,
                             bq + i*Cc, mt*128, nt*128);
    } else if (id < 144) {
        int l = id - 48, i = l / 32, r = l % 32, mt = r >> 1, nt = r & 1;
        mma_tile_run<4,64,0>(d_x2c3, K3_KV, d_wk3 + (size_t)i*Cc*K3_KV, K3_KV, 13, 0,
                             nullptr, d_khi + (size_t)i*M2*Cc, d_klo + (size_t)i*M2*Cc, 1.f,
                             bk + i*Cc, mt*128, nt*128);
    } else if (id < 240) {
        int l = id - 144, i = l / 32, r = l % 32, mt = r >> 1, nt = r & 1;
        mma_tile_run<4,64,0>(d_x2c3, K3_KV, d_wv3 + (size_t)i*Cc*K3_KV, K3_KV, 13, 0,
                             nullptr, d_vhi + (size_t)i*M2*Cc, d_vlo + (size_t)i*M2*Cc, 1.f,
                             bv + i*Cc, mt*128, nt*128);
    } else {
        int l = id - 240, i = l / 16, r = l % 16, mt = r >> 1, nt = r & 1;
        mma_tile_run<4,64,0>(d_ax13, K3_AUX, d_wva3 + (size_t)i*Cc*K3_AUX, K3_AUX, 1, 0,
                             g_vaux + (size_t)i*M1*Cc, nullptr, nullptr, 1.f,
                             nullptr, mt*128, nt*128);
    }
}

// proj (KCH=64): 64x128 tiles, split-K 4-way (3 chunks each), grid 384
__global__ __launch_bounds__(256)
void mma_proj_kernel()
{
    const int id = blockIdx.x;
    const int s = id / 96;
    const int l = id % 96;
    int i = l / 32, r = l % 32, mt = r >> 1, nt = r & 1;
    float* outp = g_pp[s] + (size_t)i*M1*Cc;
    mma_tile_run<2,64,1>(d_y3 + (size_t)i*M1*K2_Y, K2_Y, d_wp3 + (size_t)i*Cc*K3_Q, K3_Q,
                         3, s*3, outp, nullptr, nullptr, 1.f,
                         nullptr, mt*64, nt*128);
}

// ---------------- flash attention, V transposed in smem ---------------------
#define APAD 40
#define VTP 264
#define OFF_QH 0
#define OFF_QL 10240
#define OFF_KH 20480
#define OFF_KL 40960
#define OFF_VTH 61440
#define OFF_VTL 78336
#define OFF_MK 95232
#define ATTN_SMEM 99328

__global__ __launch_bounds__(256)
void attn_flash_kernel()
{
    extern __shared__ __align__(16) char dsm[];
    __nv_bfloat16 (*sQh)[APAD] = (__nv_bfloat16(*)[APAD])(dsm + OFF_QH);
    __nv_bfloat16 (*sQl)[APAD] = (__nv_bfloat16(*)[APAD])(dsm + OFF_QL);
    __nv_bfloat16 (*sKh)[APAD] = (__nv_bfloat16(*)[APAD])(dsm + OFF_KH);
    __nv_bfloat16 (*sKl)[APAD] = (__nv_bfloat16(*)[APAD])(dsm + OFF_KL);
    __nv_bfloat16 (*sVTh)[VTP] = (__nv_bfloat16(*)[VTP])(dsm + OFF_VTH);
    __nv_bfloat16 (*sVTl)[VTP] = (__nv_bfloat16(*)[VTP])(dsm + OFF_VTL);
    uint32_t (*sMask)[8] = (uint32_t(*)[8])(dsm + OFF_MK);

    const int h = blockIdx.x, b = blockIdx.y, i = blockIdx.z;
    const int tid = threadIdx.x;
    const int warp = tid >> 5, lane = tid & 31;
    const int fr = lane >> 2, qc = lane & 3;
    const int r0 = warp * 16;

    const size_t qoff = ((size_t)(i*Bz + b) * T1c) * Cc + h*32;
    const size_t koff = ((size_t)(i*Bz + b) * T2c) * Cc + h*32;

#pragma unroll
    for (int j = 0; j < 2; ++j) {
        int idx = tid + j * 256;
        int row = idx >> 2, c8 = (idx & 3) * 8;
        *(float4*)&sQh[row][c8] = *(const float4*)(d_qhi + qoff + (size_t)row*Cc + c8);
        *(float4*)&sQl[row][c8] = *(const float4*)(d_qlo + qoff + (size_t)row*Cc + c8);
    }
#pragma unroll
    for (int j = 0; j < 4; ++j) {
        int idx = tid + j * 256;
        int row = idx >> 2, c8 = (idx & 3) * 8;
        *(float4*)&sKh[row][c8] = *(const float4*)(d_khi + koff + (size_t)row*Cc + c8);
        *(float4*)&sKl[row][c8] = *(const float4*)(d_klo + koff + (size_t)row*Cc + c8);
        float4 vh4 = *(const float4*)(d_vhi + koff + (size_t)row*Cc + c8);
        float4 vl4 = *(const float4*)(d_vlo + koff + (size_t)row*Cc + c8);
        const __nv_bfloat16* vh = (const __nv_bfloat16*)&vh4;
        const __nv_bfloat16* vl = (const __nv_bfloat16*)&vl4;
#pragma unroll
        for (int jj = 0; jj < 8; ++jj) {
            sVTh[c8 + jj][row] = vh[jj];
            sVTl[c8 + jj][row] = vl[jj];
        }
    }
#pragma unroll
    for (int j = 0; j < 4; ++j) {
        int w = tid + j * 256;
        ((uint32_t*)(dsm + OFF_MK))[w] = d_maskp[(size_t)(i*Bz + b)*1024 + w];
    }
    __syncthreads();

    float m0 = -1e30f, m1 = -1e30f, l0 = 0.f, l1 = 0.f;
    float Y[4][4];
#pragma unroll
    for (int n = 0; n < 4; ++n)
#pragma unroll
        for (int q = 0; q < 4; ++q) Y[n][q] = 0.f;

    for (int ch = 0; ch < 4; ++ch) {
        float sc[8][4];
#pragma unroll
        for (int n = 0; n < 8; ++n)
#pragma unroll
            for (int q = 0; q < 4; ++q) sc[n][q] = 0.f;

#pragma unroll
        for (int term = 0; term < 3; ++term) {
            __nv_bfloat16 (*Aq)[APAD] = (term == 1) ? sQl : sQh;
            __nv_bfloat16 (*Bk)[APAD] = (term == 2) ? sKl : sKh;
#pragma unroll
            for (int kk = 0; kk < 2; ++kk) {
                const int kc = kk * 16 + qc * 2;
                uint32_t a[4];
                a[0] = *(const uint32_t*)&Aq[r0 + fr    ][kc];
                a[1] = *(const uint32_t*)&Aq[r0 + fr + 8][kc];
                a[2] = *(const uint32_t*)&Aq[r0 + fr    ][kc + 8];
                a[3] = *(const uint32_t*)&Aq[r0 + fr + 8][kc + 8];
#pragma unroll
                for (int nt = 0; nt < 8; ++nt) {
                    const int tr = ch*64 + nt*8 + fr;
                    uint32_t bb[2];
                    bb[0] = *(const uint32_t*)&Bk[tr][kc];
                    bb[1] = *(const uint32_t*)&Bk[tr][kc + 8];
                    mma16816(sc[nt], a, bb);
                }
            }
        }

        uint32_t w0a = sMask[r0 + fr    ][2*ch], w0b = sMask[r0 + fr    ][2*ch + 1];
        uint32_t w1a = sMask[r0 + fr + 8][2*ch], w1b = sMask[r0 + fr + 8][2*ch + 1];
#pragma unroll
        for (int nt = 0; nt < 8; ++nt) {
            uint32_t wr0 = (nt < 4) ? w0a : w0b;
            uint32_t wr1 = (nt < 4) ? w1a : w1b;
            const int bbase = (nt & 3) * 8 + qc * 2;
            if (!((wr0 >> bbase) & 1))       sc[nt][0] = -1e30f;
            if (!((wr0 >> (bbase+1)) & 1))   sc[nt][1] = -1e30f;
            if (!((wr1 >> bbase) & 1))       sc[nt][2] = -1e30f;
            if (!((wr1 >> (bbase+1)) & 1))   sc[nt][3] = -1e30f;
        }

        float rx0 = -1e30f, rx1 = -1e30f;
#pragma unroll
        for (int nt = 0; nt < 8; ++nt) {
            rx0 = fmaxf(rx0, fmaxf(sc[nt][0], sc[nt][1]));
            rx1 = fmaxf(rx1, fmaxf(sc[nt][2], sc[nt][3]));
        }
#pragma unroll
        for (int o = 1; o <= 2; o <<= 1) {
            rx0 = fmaxf(rx0, __shfl_xor_sync(0xffffffffu, rx0, o));
            rx1 = fmaxf(rx1, __shfl_xor_sync(0xffffffffu, rx1, o));
        }
        const float mn0 = fmaxf(m0, rx0), mn1 = fmaxf(m1, rx1);
        const float al0 = __expf(m0 - mn0), al1 = __expf(m1 - mn1);
        const float z0 = (mn0 <= -1e29f) ? 0.f : 1.f;
        const float z1 = (mn1 <= -1e29f) ? 0.f : 1.f;
        float s0 = 0.f, s1 = 0.f;
#pragma unroll
        for (int nt = 0; nt < 8; ++nt) {
            sc[nt][0] = __expf(sc[nt][0] - mn0) * z0;
            sc[nt][1] = __expf(sc[nt][1] - mn0) * z0;
            sc[nt][2] = __expf(sc[nt][2] - mn1) * z1;
            sc[nt][3] = __expf(sc[nt][3] - mn1) * z1;
            s0 += sc[nt][0] + sc[nt][1];
            s1 += sc[nt][2] + sc[nt][3];
        }
#pragma unroll
        for (int o = 1; o <= 2; o <<= 1) {
            s0 += __shfl_xor_sync(0xffffffffu, s0, o);
            s1 += __shfl_xor_sync(0xffffffffu, s1, o);
        }
        l0 = l0 * al0 + s0;
        l1 = l1 * al1 + s1;
        m0 = mn0; m1 = mn1;
#pragma unroll
        for (int n = 0; n < 4; ++n) {
            Y[n][0] *= al0; Y[n][1] *= al0;
            Y[n][2] *= al1; Y[n][3] *= al1;
        }

        uint32_t ah[4][4], alo[4][4];
#pragma unroll
        for (int kt = 0; kt < 4; ++kt) {
            const int f0 = 2*kt, f1 = 2*kt + 1;
            ah[kt][0] = pack_bf2(sc[f0][0], sc[f0][1]);
            ah[kt][1] = pack_bf2(sc[f0][2], sc[f0][3]);
            ah[kt][2] = pack_bf2(sc[f1][0], sc[f1][1]);
            ah[kt][3] = pack_bf2(sc[f1][2], sc[f1][3]);
            alo[kt][0] = pack_bf2_res(sc[f0][0], sc[f0][1], ah[kt][0]);
            alo[kt][1] = pack_bf2_res(sc[f0][2], sc[f0][3], ah[kt][1]);
            alo[kt][2] = pack_bf2_res(sc[f1][0], sc[f1][1], ah[kt][2]);
            alo[kt][3] = pack_bf2_res(sc[f1][2], sc[f1][3], ah[kt][3]);
        }

#pragma unroll
        for (int term = 0; term < 3; ++term) {
            uint32_t (*Ap)[4] = (term == 1) ? alo : ah;
            __nv_bfloat16 (*Bv)[VTP] = (term == 2) ? sVTl : sVTh;
#pragma unroll
            for (int kt = 0; kt < 4; ++kt) {
#pragma unroll
                for (int nt = 0; nt < 4; ++nt) {
                    const int k0 = ch*64 + kt*16 + qc*2;
                    const int n  = nt*8 + fr;
                    uint32_t bb[2];
                    bb[0] = *(const uint32_t*)&Bv[n][k0];
                    bb[1] = *(const uint32_t*)&Bv[n][k0 + 8];
                    mma16816(Y[nt], Ap[kt], bb);
                }
            }
        }
    }

    float inv0 = (l0 > 0.f) ? 1.f / l0 : 0.f;
    float inv1 = (l1 > 0.f) ? 1.f / l1 : 0.f;
    if (l0 == 0.f) {
#pragma unroll
        for (int nt = 0; nt < 4; ++nt)
            for (int jj = 0; jj < 2; ++jj) {
                int col = nt*8 + qc*2 + jj;
                float s = 0.f;
                for (int t = 0; t < 256; ++t)
                    s += __bfloat162float(sVTh[col][t]) + __bfloat162float(sVTl[col][t]);
                Y[nt][jj] = s * (1.f/256.f);
            }
        inv0 = 1.f;
    }
    if (l1 == 0.f) {
#pragma unroll
        for (int nt = 0; nt < 4; ++nt)
            for (int jj = 0; jj < 2; ++jj) {
                int col = nt*8 + qc*2 + jj;
                float s = 0.f;
                for (int t = 0; t < 256; ++t)
                    s += __bfloat162float(sVTh[col][t]) + __bfloat162float(sVTl[col][t]);
                Y[nt][2 + jj] = s * (1.f/256.f);
            }
        inv1 = 1.f;
    }

    const int row0 = r0 + fr, row1 = r0 + fr + 8;
    const float* vx0 = g_vaux + ((size_t)(i*Bz + b)*T1c + row0) * Cc + h*32;
    const float* vx1 = g_vaux + ((size_t)(i*Bz + b)*T1c + row1) * Cc + h*32;
    __nv_bfloat16* y0 = d_y3 + (size_t)i*M1*K2_Y + (size_t)(b*T1c + row0)*K2_Y + h*32;
    __nv_bfloat16* y1 = d_y3 + (size_t)i*M1*K2_Y + (size_t)(b*T1c + row1)*K2_Y + h*32;
#pragma unroll
    for (int nt = 0; nt < 4; ++nt) {
        const int c0 = nt*8 + qc*2;
        float2 v0 = *(const float2*)(vx0 + c0);
        float2 v1 = *(const float2*)(vx1 + c0);
        float o00 = Y[nt][0]*inv0 + v0.x, o01 = Y[nt][1]*inv0 + v0.y;
        float o10 = Y[nt][2]*inv1 + v1.x, o11 = Y[nt][3]*inv1 + v1.y;
        uint32_t h0 = pack_bf2(o00, o01), l0p = pack_bf2_res(o00, o01, h0);
        uint32_t h1 = pack_bf2(o10, o11), l1p = pack_bf2_res(o10, o11, h1);
        *(uint32_t*)(y0 + c0)       = h0;
        *(uint32_t*)(y0 + 256 + c0) = l0p;
        *(uint32_t*)(y1 + c0)       = h1;
        *(uint32_t*)(y1 + 256 + c0) = l1p;
    }
}

// ---------------- final sum: 12 planes + biases ----------------
__global__ void sum_kernel(const float* __restrict__ bp, float* __restrict__ out)
{
    int e = blockIdx.x * 256 + threadIdx.x;
    int col4 = (e & 63) * 4;
    float4 o = make_float4(0.f, 0.f, 0.f, 0.f);
#pragma unroll
    for (int i = 0; i < NT; ++i) {
        float4 bi = *(const float4*)(bp + i*256 + col4);
        o.x += bi.x; o.y += bi.y; o.z += bi.z; o.w += bi.w;
#pragma unroll
        for (int s = 0; s < 4; ++s) {
            float4 pa = *(const float4*)(g_pp[s] + (size_t)i*M1*Cc + (size_t)e*4);
            o.x += pa.x; o.y += pa.y; o.z += pa.z; o.w += pa.w;
        }
    }
    *(float4*)(out + (size_t)e*4) = o;
}

// ---------------- launch ----------------
extern "C" void kernel_launch(void* const* d_in, const int* in_sizes, int n_in,
                              void* d_out, int out_size)
{
    const float* x1     = (const float*)d_in[0];
    const float* x2     = (const float*)d_in[1];
    const float* aux_x1 = (const float*)d_in[2];
    const float* aux_x2 = (const float*)d_in[3];
    const int*   masks  = (const int*)  d_in[4];
    const float* Wq     = (const float*)d_in[5];
    const float* bq     = (const float*)d_in[6];
    const float* Wk     = (const float*)d_in[7];
    const float* bk     = (const float*)d_in[8];
    const float* Wv     = (const float*)d_in[9];
    const float* bv     = (const float*)d_in[10];
    const float* Wp     = (const float*)d_in[11];
    const float* bp     = (const float*)d_in[12];
    float* out = (float*)d_out;

    cudaFuncSetAttribute(attn_flash_kernel,
                         cudaFuncAttributeMaxDynamicSharedMemorySize, ATTN_SMEM);
    cudaFuncSetAttribute(mma_qkv_kernel,
                         cudaFuncAttributeMaxDynamicSharedMemorySize, QKV_SMEM);
    cudaFuncSetAttribute(mma_proj_kernel,
                         cudaFuncAttributeMaxDynamicSharedMemorySize, PROJ_SMEM);

    prep_all_kernel<<<PREP_GRID, 256>>>(x1, x2, aux_x1, aux_x2, Wq, Wk, Wv, Wp, masks);
    mma_qkv_kernel<<<288, 256, QKV_SMEM>>>(bq, bk, bv);
    attn_flash_kernel<<<dim3(8, Bz, NT), 256, ATTN_SMEM>>>();
    mma_proj_kernel<<<384, 256, PROJ_SMEM>>>();
    sum_kernel<<<256, 256>>>(bp, out);
}